// round 13
// baseline (speedup 1.0000x reference)
#include <cuda_runtime.h>
#include <cuda_fp16.h>
#include <cstdint>
#include <cstddef>

constexpr int B_ = 2, N_ = 3072, C_ = 768, H_ = 12, HD_ = 64;
constexpr int M_ = B_ * N_;           // 6144
constexpr int QKVD = 3 * C_;          // 2304

// ---- static scratch ----
__device__ __half g_xnh[M_ * C_];
__device__ __half g_qkvh[(size_t)M_ * QKVD];
__device__ __half g_attnh[M_ * C_];
__device__ float  g_x1[M_ * C_];
__device__ __half g_hh[(size_t)M_ * 4 * C_];
__device__ __half g_wqkvh[QKVD * C_];
__device__ __half g_wprojh[C_ * C_];
__device__ __half g_wfc1h[4 * C_ * C_];
__device__ __half g_wfc2h[C_ * 4 * C_];
__device__ int    g_attn_ctr;

// ---- ptx helpers ----
__device__ __forceinline__ void mma_f16(float* d, const uint32_t* a,
                                        const uint32_t* b, const float* c) {
    asm volatile(
        "mma.sync.aligned.m16n8k16.row.col.f32.f16.f16.f32 "
        "{%0,%1,%2,%3},{%4,%5,%6,%7},{%8,%9},{%10,%11,%12,%13};"
        : "=f"(d[0]), "=f"(d[1]), "=f"(d[2]), "=f"(d[3])
        : "r"(a[0]), "r"(a[1]), "r"(a[2]), "r"(a[3]),
          "r"(b[0]), "r"(b[1]),
          "f"(c[0]), "f"(c[1]), "f"(c[2]), "f"(c[3]));
}
// fp16 accumulator variant (2 output regs)
__device__ __forceinline__ void mma_h16(uint32_t* d, const uint32_t* a,
                                        const uint32_t* b, const uint32_t* c) {
    asm volatile(
        "mma.sync.aligned.m16n8k16.row.col.f16.f16.f16.f16 "
        "{%0,%1},{%2,%3,%4,%5},{%6,%7},{%8,%9};"
        : "=r"(d[0]), "=r"(d[1])
        : "r"(a[0]), "r"(a[1]), "r"(a[2]), "r"(a[3]),
          "r"(b[0]), "r"(b[1]), "r"(c[0]), "r"(c[1]));
}
__device__ __forceinline__ void ldsm4(uint32_t* r, uint32_t a) {
    asm volatile("ldmatrix.sync.aligned.m8n8.x4.shared.b16 {%0,%1,%2,%3}, [%4];"
                 : "=r"(r[0]), "=r"(r[1]), "=r"(r[2]), "=r"(r[3]) : "r"(a));
}
__device__ __forceinline__ void ldsm4t(uint32_t* r, uint32_t a) {
    asm volatile("ldmatrix.sync.aligned.m8n8.x4.trans.shared.b16 {%0,%1,%2,%3}, [%4];"
                 : "=r"(r[0]), "=r"(r[1]), "=r"(r[2]), "=r"(r[3]) : "r"(a));
}
__device__ __forceinline__ void cpa16(uint32_t dst, const void* src) {
    asm volatile("cp.async.cg.shared.global [%0], [%1], 16;\n" :: "r"(dst), "l"(src));
}
#define CP_COMMIT() asm volatile("cp.async.commit_group;\n" ::: "memory")
#define CP_WAIT1()  asm volatile("cp.async.wait_group 1;\n" ::: "memory")
#define CP_WAIT0()  asm volatile("cp.async.wait_group 0;\n" ::: "memory")

__device__ __forceinline__ uint32_t h2u(half2 h) { return *(uint32_t*)&h; }
__device__ __forceinline__ half2 u2h(uint32_t u) { return *(half2*)&u; }
__device__ __forceinline__ uint32_t ex2h2(uint32_t x) {
    uint32_t r;
    asm("ex2.approx.f16x2 %0, %1;" : "=r"(r) : "r"(x));
    return r;
}

// ============================================================
// fused fp32 -> fp16 conversion for all 4 weight matrices
// ============================================================
constexpr int N8_QKV = QKVD * C_ / 8;
constexpr int N8_PRJ = C_ * C_ / 8;
constexpr int N8_FC  = 4 * C_ * C_ / 8;
constexpr int N8_TOT = N8_QKV + N8_PRJ + 2 * N8_FC;

__global__ void f2h_all(const float* __restrict__ s0, const float* __restrict__ s1,
                        const float* __restrict__ s2, const float* __restrict__ s3,
                        __half* __restrict__ d0, __half* __restrict__ d1,
                        __half* __restrict__ d2, __half* __restrict__ d3) {
    int i = blockIdx.x * blockDim.x + threadIdx.x;
    if (i >= N8_TOT) return;
    const float* s; __half* d;
    if (i < N8_QKV)                       { s = s0; d = d0; }
    else if (i < N8_QKV + N8_PRJ)         { s = s1; d = d1; i -= N8_QKV; }
    else if (i < N8_QKV + N8_PRJ + N8_FC) { s = s2; d = d2; i -= N8_QKV + N8_PRJ; }
    else                                  { s = s3; d = d3; i -= N8_QKV + N8_PRJ + N8_FC; }
    const float4* sp = (const float4*)s;
    float4 a = sp[2 * i], b = sp[2 * i + 1];
    half2 h[4] = {__floats2half2_rn(a.x, a.y), __floats2half2_rn(a.z, a.w),
                  __floats2half2_rn(b.x, b.y), __floats2half2_rn(b.z, b.w)};
    ((uint4*)d)[i] = *(uint4*)h;
}

// ============================================================
// LayerNorm: one WARP per row (no block barriers / smem).
// 256 threads = 8 rows per block. Also resets attn counter.
// ============================================================
__global__ void ln_h(const float* __restrict__ x, const float* __restrict__ g,
                     const float* __restrict__ b, __half* __restrict__ out) {
    const int lane = threadIdx.x & 31;
    const int row = blockIdx.x * 8 + (threadIdx.x >> 5);
    if (row == 0 && lane == 0) g_attn_ctr = 0;

    const float2* xr = (const float2*)(x + (size_t)row * C_);
    float2 v[12];
    float s = 0.f, sq = 0.f;
#pragma unroll
    for (int j = 0; j < 12; j++) {
        v[j] = xr[lane + j * 32];
        s += v[j].x + v[j].y;
        sq += v[j].x * v[j].x + v[j].y * v[j].y;
    }
#pragma unroll
    for (int o = 16; o > 0; o >>= 1) {
        s  += __shfl_xor_sync(0xffffffffu, s, o);
        sq += __shfl_xor_sync(0xffffffffu, sq, o);
    }
    float mean = s * (1.0f / C_);
    float rstd = rsqrtf(sq * (1.0f / C_) - mean * mean + 1e-5f);
    half2* orow = (half2*)(out + (size_t)row * C_);
    const float2* gp = (const float2*)g;
    const float2* bp = (const float2*)b;
#pragma unroll
    for (int j = 0; j < 12; j++) {
        float2 gg = gp[lane + j * 32];
        float2 bb = bp[lane + j * 32];
        orow[lane + j * 32] = __floats2half2_rn(
            (v[j].x - mean) * rstd * gg.x + bb.x,
            (v[j].y - mean) * rstd * gg.y + bb.y);
    }
}

// ============================================================
// fp16 tensor-core GEMM NT: 128x128x64 block tile, 4 warps (2x2),
// warp tile 64x64, 3-stage cp.async, 2 blocks/SM.
// BK=64: one barrier per 128 mma/warp (half the syncs of BK=32).
// ROPE=1: fused 2D rope on q/k sections of QKV output (OUTH=1).
// ============================================================
constexpr int ASTR = 72;                   // halves per smem row (64 + pad 8)
constexpr int A_STG = 128 * ASTR;          // halves per stage per matrix
constexpr int SMEM_GEMM = 3 * 2 * A_STG * 2;   // 110592 bytes

template <int ACT, int OUTH, int ROPE>
__global__ void __launch_bounds__(128, 2)
gemm_h(const __half* __restrict__ A, const __half* __restrict__ W,
       const float* __restrict__ bias, const float* __restrict__ resid,
       void* __restrict__ Cout, int M, int Nd, int K,
       const float* __restrict__ cx, const float* __restrict__ sx,
       const float* __restrict__ cy, const float* __restrict__ sy)
{
    extern __shared__ __half sm[];
    __half* As = sm;                    // 3 stages of 128x64 (stride 72)
    __half* Ws = sm + 3 * A_STG;

    const int tid = threadIdx.x, lane = tid & 31, wid = tid >> 5;
    const int warpM = wid >> 1, warpN = wid & 1;
    const int g = lane >> 2, q = lane & 3;
    const int m0 = blockIdx.y * 128, n0 = blockIdx.x * 128;

    const uint32_t asbase = (uint32_t)__cvta_generic_to_shared(As);
    const uint32_t wsbase = (uint32_t)__cvta_generic_to_shared(Ws);

    auto stage = [&](int t, int s) {
        int k0 = t * 64;
        uint32_t ab = asbase + s * (A_STG * 2);
        uint32_t wb = wsbase + s * (A_STG * 2);
#pragma unroll
        for (int i = 0; i < 8; i++) {
            int idx = tid + i * 128;
            int r = idx >> 3, c = (idx & 7) * 8;
            cpa16(ab + (r * ASTR + c) * 2, A + (size_t)(m0 + r) * K + k0 + c);
            cpa16(wb + (r * ASTR + c) * 2, W + (size_t)(n0 + r) * K + k0 + c);
        }
        CP_COMMIT();
    };

    float acc[4][8][4];
#pragma unroll
    for (int mt = 0; mt < 4; mt++)
#pragma unroll
        for (int nt = 0; nt < 8; nt++)
#pragma unroll
            for (int r = 0; r < 4; r++) acc[mt][nt][r] = 0.f;

    const int T = K / 64;
    stage(0, 0);
    stage(1, 1);

    const int lrow = warpM * 64 + (lane & 7) + ((lane >> 3) & 1) * 8;
    const int lcol = (lane >> 4) * 8;
    const int brow = (lane & 7) + ((lane >> 4) & 1) * 8;
    const int bcol = ((lane >> 3) & 1) * 8;

    for (int t = 0; t < T; t++) {
        if (t + 1 < T) CP_WAIT1(); else CP_WAIT0();
        __syncthreads();
        if (t + 2 < T) stage(t + 2, (t + 2) % 3);
        const int s = t % 3;
        const uint32_t ab = asbase + s * (A_STG * 2);
        const uint32_t wb = wsbase + s * (A_STG * 2);
#pragma unroll
        for (int kk = 0; kk < 64; kk += 16) {
            uint32_t af[4][4];
#pragma unroll
            for (int mt = 0; mt < 4; mt++)
                ldsm4(af[mt], ab + ((lrow + mt * 16) * ASTR + lcol + kk) * 2);
            uint32_t bf[8][2];
#pragma unroll
            for (int ntp = 0; ntp < 4; ntp++) {
                uint32_t r[4];
                ldsm4(r, wb + ((warpN * 64 + ntp * 16 + brow) * ASTR + kk + bcol) * 2);
                bf[2 * ntp][0] = r[0]; bf[2 * ntp][1] = r[1];
                bf[2 * ntp + 1][0] = r[2]; bf[2 * ntp + 1][1] = r[3];
            }
#pragma unroll
            for (int mt = 0; mt < 4; mt++)
#pragma unroll
                for (int nt = 0; nt < 8; nt++)
                    mma_f16(acc[mt][nt], af[mt], bf[nt], acc[mt][nt]);
        }
    }

    if (ROPE) {
        __half* O = (__half*)Cout;
        const int chunk = n0 + warpN * 64;
        const bool qk = chunk < 2 * C_;
#pragma unroll
        for (int mt = 0; mt < 4; mt++) {
            int m = m0 + warpM * 64 + mt * 16 + g;
            int ntok = m % N_;
            if (qk) {
#pragma unroll
                for (int base = 0; base < 8; base += 4) {
                    const float* ct = base ? cx : cy;
                    const float* st = base ? sx : sy;
#pragma unroll
                    for (int p = 0; p < 2; p++) {
                        int j = p * 8 + 2 * q;
                        float2 c0 = *(const float2*)&ct[ntok * 32 + j];
                        float2 s0 = *(const float2*)&st[ntok * 32 + j];
                        float2 c1 = *(const float2*)&ct[(ntok + 8) * 32 + j];
                        float2 s1 = *(const float2*)&st[(ntok + 8) * 32 + j];
                        float* lo = acc[mt][base + p];
                        float* hi = acc[mt][base + p + 2];
                        float t1, t2;
                        t1 = lo[0]; t2 = hi[0];
                        lo[0] = t1 * c0.x - t2 * s0.x; hi[0] = t2 * c0.x + t1 * s0.x;
                        t1 = lo[1]; t2 = hi[1];
                        lo[1] = t1 * c0.y - t2 * s0.y; hi[1] = t2 * c0.y + t1 * s0.y;
                        t1 = lo[2]; t2 = hi[2];
                        lo[2] = t1 * c1.x - t2 * s1.x; hi[2] = t2 * c1.x + t1 * s1.x;
                        t1 = lo[3]; t2 = hi[3];
                        lo[3] = t1 * c1.y - t2 * s1.y; hi[3] = t2 * c1.y + t1 * s1.y;
                    }
                }
            }
#pragma unroll
            for (int nt = 0; nt < 8; nt++) {
                int c = chunk + nt * 8 + 2 * q;
                size_t i0 = (size_t)m * Nd + c, i1 = (size_t)(m + 8) * Nd + c;
                *(half2*)(O + i0) = __floats2half2_rn(acc[mt][nt][0], acc[mt][nt][1]);
                *(half2*)(O + i1) = __floats2half2_rn(acc[mt][nt][2], acc[mt][nt][3]);
            }
        }
        return;
    }

#pragma unroll
    for (int mt = 0; mt < 4; mt++) {
#pragma unroll
        for (int nt = 0; nt < 8; nt++) {
            int m = m0 + warpM * 64 + mt * 16 + g;
            int c = n0 + warpN * 64 + nt * 8 + 2 * q;
            float bv0 = bias ? bias[c] : 0.f;
            float bv1 = bias ? bias[c + 1] : 0.f;
            float v0 = acc[mt][nt][0] + bv0, v1 = acc[mt][nt][1] + bv1;
            float v2 = acc[mt][nt][2] + bv0, v3 = acc[mt][nt][3] + bv1;
            if (ACT == 1) {
                v0 = 0.5f * v0 * (1.0f + erff(v0 * 0.70710678118654752f));
                v1 = 0.5f * v1 * (1.0f + erff(v1 * 0.70710678118654752f));
                v2 = 0.5f * v2 * (1.0f + erff(v2 * 0.70710678118654752f));
                v3 = 0.5f * v3 * (1.0f + erff(v3 * 0.70710678118654752f));
            }
            size_t i0 = (size_t)m * Nd + c, i1 = (size_t)(m + 8) * Nd + c;
            if (OUTH) {
                __half* O = (__half*)Cout;
                *(half2*)(O + i0) = __floats2half2_rn(v0, v1);
                *(half2*)(O + i1) = __floats2half2_rn(v2, v3);
            } else {
                float* O = (float*)Cout;
                if (resid) {
                    float2 r0 = *(const float2*)&resid[i0];
                    float2 r1 = *(const float2*)&resid[i1];
                    v0 += r0.x; v1 += r0.y; v2 += r1.x; v3 += r1.y;
                }
                *(float2*)&O[i0] = make_float2(v0, v1);
                *(float2*)&O[i1] = make_float2(v2, v3);
            }
        }
    }
}

// ============================================================
// Flash attention, persistent work-stealing blocks.  (R11-proven)
// 4 warps/block, 32 q-rows per warp (128 rows per item),
// Q staged in smem (raw), S in fp16 accumulators,
// 3-stage K/V cp.async ring, one barrier per tile, 3 CTAs/SM.
// ============================================================
constexpr int KSTR = 72;
constexpr int ATTN_ITEMS = B_ * H_ * (N_ / 128);   // 576
constexpr int Q_OFF = 0;                           // halves
constexpr int K_OFF = 128 * KSTR;                  // 9216
constexpr int V_OFF = K_OFF + 3 * 64 * KSTR;       // 23040
constexpr int SMEM_ATTN = (V_OFF + 3 * 64 * KSTR) * 2;  // 73728 bytes

__global__ void __launch_bounds__(128, 3)
attn_h(const __half* __restrict__ qkvh, __half* __restrict__ outh)
{
    extern __shared__ __half smA[];
    __shared__ int s_idx;

    const int tid = threadIdx.x, lane = tid & 31, wid = tid >> 5;
    const int g = lane >> 2, q = lane & 3;

    const uint32_t base = (uint32_t)__cvta_generic_to_shared(smA);
    const uint32_t qsb = base + Q_OFF * 2;
    const uint32_t ksb = base + K_OFF * 2;
    const uint32_t vsb = base + V_OFF * 2;

    const int qlrow = wid * 32 + (lane & 7) + ((lane >> 3) & 1) * 8;
    const int qlcol = (lane >> 4) * 8;
    const int brow = (lane & 7) + ((lane >> 4) & 1) * 8;
    const int bcol = ((lane >> 3) & 1) * 8;
    const int vrow = (lane & 7) + ((lane >> 3) & 1) * 8;
    const int vcol = ((lane >> 4) & 1) * 8;

    const float SC = 0.125f * 1.44269504088896341f;
    const half2 sc2 = __float2half2_rn(SC);
    const uint32_t ones2[2] = {0x3C003C00u, 0x3C003C00u};
    constexpr int T = N_ / 64;   // 48

    for (;;) {
        if (tid == 0) s_idx = atomicAdd(&g_attn_ctr, 1);
        __syncthreads();
        const int item = s_idx;
        if (item >= ATTN_ITEMS) break;
        const int bh = item / (N_ / 128);
        const int qb = item % (N_ / 128);
        const int b = bh / H_, h = bh % H_;

        const size_t qgbase = ((size_t)(b * N_ + qb * 128)) * QKVD + h * HD_;
        const size_t kgbase = (size_t)(b * N_) * QKVD + C_ + h * HD_;
        const size_t vgbase = kgbase + C_;

        auto stage = [&](int kt, int buf) {
#pragma unroll
            for (int i = 0; i < 4; i++) {
                int idx = tid + i * 128;
                int r = idx >> 3, c = idx & 7;
                size_t roff = (size_t)(kt + r) * QKVD + c * 8;
                cpa16(ksb + (buf * 64 * KSTR + r * KSTR + c * 8) * 2, qkvh + kgbase + roff);
                cpa16(vsb + (buf * 64 * KSTR + r * KSTR + c * 8) * 2, qkvh + vgbase + roff);
            }
            CP_COMMIT();
        };

#pragma unroll
        for (int i = 0; i < 8; i++) {
            int idx = tid + i * 128;
            int r = idx >> 3, c = idx & 7;
            cpa16(qsb + (r * KSTR + c * 8) * 2, qkvh + qgbase + (size_t)r * QKVD + c * 8);
        }
        stage(0, 0);
        stage(64, 1);

        float o[2][8][4];
#pragma unroll
        for (int mt = 0; mt < 2; mt++)
#pragma unroll
            for (int nt = 0; nt < 8; nt++)
#pragma unroll
                for (int r = 0; r < 4; r++) o[mt][nt][r] = 0.f;
        float mv[2][2] = {{-1e30f, -1e30f}, {-1e30f, -1e30f}};
        float lv[2][2] = {{0.f, 0.f}, {0.f, 0.f}};

        for (int t = 0; t < T; t++) {
            if (t + 1 < T) CP_WAIT1(); else CP_WAIT0();
            __syncthreads();
            if (t + 2 < T) stage((t + 2) * 64, (t + 2) % 3);

            const uint32_t kb = ksb + (t % 3) * (64 * KSTR * 2);
            const uint32_t vb = vsb + (t % 3) * (64 * KSTR * 2);

            uint32_t s[2][8][2];
#pragma unroll
            for (int mt = 0; mt < 2; mt++)
#pragma unroll
                for (int nt = 0; nt < 8; nt++) { s[mt][nt][0] = 0u; s[mt][nt][1] = 0u; }
#pragma unroll
            for (int ks = 0; ks < 4; ks++) {
                uint32_t aq[2][4];
#pragma unroll
                for (int mt = 0; mt < 2; mt++)
                    ldsm4(aq[mt], qsb + ((qlrow + mt * 16) * KSTR + ks * 16 + qlcol) * 2);
#pragma unroll
                for (int ntp = 0; ntp < 4; ntp++) {
                    uint32_t r[4];
                    ldsm4(r, kb + ((ntp * 16 + brow) * KSTR + ks * 16 + bcol) * 2);
#pragma unroll
                    for (int mt = 0; mt < 2; mt++) {
                        mma_h16(s[mt][2 * ntp],     aq[mt], r,     s[mt][2 * ntp]);
                        mma_h16(s[mt][2 * ntp + 1], aq[mt], r + 2, s[mt][2 * ntp + 1]);
                    }
                }
            }

            float al[2][2];
#pragma unroll
            for (int mt = 0; mt < 2; mt++) {
                half2 hx0 = u2h(s[mt][0][0]), hx1 = u2h(s[mt][0][1]);
#pragma unroll
                for (int nt = 1; nt < 8; nt++) {
                    hx0 = __hmax2(hx0, u2h(s[mt][nt][0]));
                    hx1 = __hmax2(hx1, u2h(s[mt][nt][1]));
                }
                float mx0 = fmaxf(__low2float(hx0), __high2float(hx0));
                float mx1 = fmaxf(__low2float(hx1), __high2float(hx1));
                mx0 = fmaxf(mx0, __shfl_xor_sync(0xffffffffu, mx0, 1));
                mx0 = fmaxf(mx0, __shfl_xor_sync(0xffffffffu, mx0, 2));
                mx1 = fmaxf(mx1, __shfl_xor_sync(0xffffffffu, mx1, 1));
                mx1 = fmaxf(mx1, __shfl_xor_sync(0xffffffffu, mx1, 2));

                float nm0 = fmaxf(mv[mt][0], mx0), nm1 = fmaxf(mv[mt][1], mx1);
                float a0 = exp2f((mv[mt][0] - nm0) * SC);
                float a1 = exp2f((mv[mt][1] - nm1) * SC);
                mv[mt][0] = nm0; mv[mt][1] = nm1;
                al[mt][0] = a0; al[mt][1] = a1;

                if (!__all_sync(0xffffffffu, (a0 == 1.f) & (a1 == 1.f))) {
#pragma unroll
                    for (int nt = 0; nt < 8; nt++) {
                        o[mt][nt][0] *= a0; o[mt][nt][1] *= a0;
                        o[mt][nt][2] *= a1; o[mt][nt][3] *= a1;
                    }
                }
                half2 nm02 = __float2half2_rn(nm0);
                half2 nm12 = __float2half2_rn(nm1);
#pragma unroll
                for (int nt = 0; nt < 8; nt++) {
                    s[mt][nt][0] = ex2h2(h2u(__hmul2(__hsub2(u2h(s[mt][nt][0]), nm02), sc2)));
                    s[mt][nt][1] = ex2h2(h2u(__hmul2(__hsub2(u2h(s[mt][nt][1]), nm12), sc2)));
                }
            }

            float fs[2][4] = {{0.f, 0.f, 0.f, 0.f}, {0.f, 0.f, 0.f, 0.f}};
#pragma unroll
            for (int k2 = 0; k2 < 4; k2++) {
                uint32_t af[2][4];
#pragma unroll
                for (int mt = 0; mt < 2; mt++) {
                    af[mt][0] = s[mt][2 * k2][0];     af[mt][1] = s[mt][2 * k2][1];
                    af[mt][2] = s[mt][2 * k2 + 1][0]; af[mt][3] = s[mt][2 * k2 + 1][1];
                    mma_f16(fs[mt], af[mt], ones2, fs[mt]);
                }
#pragma unroll
                for (int ntp = 0; ntp < 4; ntp++) {
                    uint32_t r[4];
                    ldsm4t(r, vb + ((k2 * 16 + vrow) * KSTR + ntp * 16 + vcol) * 2);
#pragma unroll
                    for (int mt = 0; mt < 2; mt++) {
                        mma_f16(o[mt][2 * ntp],     af[mt], r,     o[mt][2 * ntp]);
                        mma_f16(o[mt][2 * ntp + 1], af[mt], r + 2, o[mt][2 * ntp + 1]);
                    }
                }
            }
#pragma unroll
            for (int mt = 0; mt < 2; mt++) {
                lv[mt][0] = lv[mt][0] * al[mt][0] + fs[mt][0];
                lv[mt][1] = lv[mt][1] * al[mt][1] + fs[mt][2];
            }
        }

        const int qrow = qb * 128 + wid * 32 + g;
#pragma unroll
        for (int mt = 0; mt < 2; mt++) {
            float inv0 = 1.f / lv[mt][0], inv1 = 1.f / lv[mt][1];
            __half* o0 = outh + (size_t)(b * N_ + qrow + mt * 16) * C_ + h * HD_;
            __half* o1 = o0 + (size_t)8 * C_;
#pragma unroll
            for (int nt = 0; nt < 8; nt++) {
                int c = nt * 8 + 2 * q;
                *(half2*)(o0 + c) = __floats2half2_rn(o[mt][nt][0] * inv0, o[mt][nt][1] * inv0);
                *(half2*)(o1 + c) = __floats2half2_rn(o[mt][nt][2] * inv1, o[mt][nt][3] * inv1);
            }
        }
    }
}

// ============================================================
// Launch orchestration
// ============================================================
extern "C" void kernel_launch(void* const* d_in, const int* in_sizes, int n_in,
                              void* d_out, int out_size) {
    const float* x      = (const float*)d_in[0];
    const float* w_qkv  = (const float*)d_in[1];
    const float* w_proj = (const float*)d_in[2];
    const float* b_proj = (const float*)d_in[3];
    const float* g1     = (const float*)d_in[4];
    const float* beta1  = (const float*)d_in[5];
    const float* g2     = (const float*)d_in[6];
    const float* beta2  = (const float*)d_in[7];
    const float* w_fc1  = (const float*)d_in[8];
    const float* b_fc1  = (const float*)d_in[9];
    const float* w_fc2  = (const float*)d_in[10];
    const float* b_fc2  = (const float*)d_in[11];
    const float* cos_x  = (const float*)d_in[12];
    const float* sin_x  = (const float*)d_in[13];
    const float* cos_y  = (const float*)d_in[14];
    const float* sin_y  = (const float*)d_in[15];
    float* out = (float*)d_out;

    __half *xnh, *qkvh, *attnh, *hh, *wqkvh, *wprojh, *wfc1h, *wfc2h;
    float* x1;
    cudaGetSymbolAddress((void**)&xnh,   g_xnh);
    cudaGetSymbolAddress((void**)&qkvh,  g_qkvh);
    cudaGetSymbolAddress((void**)&attnh, g_attnh);
    cudaGetSymbolAddress((void**)&x1,    g_x1);
    cudaGetSymbolAddress((void**)&hh,    g_hh);
    cudaGetSymbolAddress((void**)&wqkvh, g_wqkvh);
    cudaGetSymbolAddress((void**)&wprojh, g_wprojh);
    cudaGetSymbolAddress((void**)&wfc1h, g_wfc1h);
    cudaGetSymbolAddress((void**)&wfc2h, g_wfc2h);

    cudaFuncSetAttribute(gemm_h<0, 1, 1>, cudaFuncAttributeMaxDynamicSharedMemorySize, SMEM_GEMM);
    cudaFuncSetAttribute(gemm_h<0, 0, 0>, cudaFuncAttributeMaxDynamicSharedMemorySize, SMEM_GEMM);
    cudaFuncSetAttribute(gemm_h<1, 1, 0>, cudaFuncAttributeMaxDynamicSharedMemorySize, SMEM_GEMM);
    cudaFuncSetAttribute(attn_h, cudaFuncAttributeMaxDynamicSharedMemorySize, SMEM_ATTN);

    // weight conversions (single launch)
    f2h_all<<<(N8_TOT + 255) / 256, 256>>>(w_qkv, w_proj, w_fc1, w_fc2,
                                           wqkvh, wprojh, wfc1h, wfc2h);

    // 1. LN1 -> half (also zeroes the attn work counter)
    ln_h<<<M_ / 8, 256>>>(x, g1, beta1, xnh);
    // 2. QKV projection + fused 2D RoPE -> half
    gemm_h<0, 1, 1><<<dim3(QKVD / 128, M_ / 128), 128, SMEM_GEMM>>>(
        xnh, wqkvh, nullptr, nullptr, qkvh, M_, QKVD, C_, cos_x, sin_x, cos_y, sin_y);
    // 3. Attention -> half (persistent, work-stealing)
    attn_h<<<456, 128, SMEM_ATTN>>>(qkvh, attnh);
    // 4. proj + bias + residual(x) -> x1 (fp32)
    gemm_h<0, 0, 0><<<dim3(C_ / 128, M_ / 128), 128, SMEM_GEMM>>>(
        attnh, wprojh, b_proj, x, x1, M_, C_, C_, nullptr, nullptr, nullptr, nullptr);
    // 5. LN2 -> half
    ln_h<<<M_ / 8, 256>>>(x1, g2, beta2, xnh);
    // 6. FC1 + bias + GELU -> half
    gemm_h<1, 1, 0><<<dim3(4 * C_ / 128, M_ / 128), 128, SMEM_GEMM>>>(
        xnh, wfc1h, b_fc1, nullptr, hh, M_, 4 * C_, C_, nullptr, nullptr, nullptr, nullptr);
    // 7. FC2 + bias + residual(x1) -> out (fp32)
    gemm_h<0, 0, 0><<<dim3(C_ / 128, M_ / 128), 128, SMEM_GEMM>>>(
        hh, wfc2h, b_fc2, x1, out, M_, C_, 4 * C_, nullptr, nullptr, nullptr, nullptr);
}

// round 14
// speedup vs baseline: 1.0258x; 1.0258x over previous
#include <cuda_runtime.h>
#include <cuda_fp16.h>
#include <cstdint>
#include <cstddef>

constexpr int B_ = 2, N_ = 3072, C_ = 768, H_ = 12, HD_ = 64;
constexpr int M_ = B_ * N_;           // 6144
constexpr int QKVD = 3 * C_;          // 2304

// ---- static scratch ----
__device__ __half g_xnh[M_ * C_];
__device__ __half g_qkvh[(size_t)M_ * QKVD];
__device__ __half g_attnh[M_ * C_];
__device__ float  g_x1[M_ * C_];
__device__ __half g_hh[(size_t)M_ * 4 * C_];
__device__ __half g_wqkvh[QKVD * C_];
__device__ __half g_wprojh[C_ * C_];
__device__ __half g_wfc1h[4 * C_ * C_];
__device__ __half g_wfc2h[C_ * 4 * C_];
__device__ int    g_attn_ctr;
// split-KV partials
constexpr int ATTN_ITEMS = B_ * H_ * (N_ / 128) * 2;   // 1152
__device__ __half g_po[(size_t)ATTN_ITEMS * 128 * 64]; // normalized partial O
__device__ float  g_pm[ATTN_ITEMS * 128];
__device__ float  g_pl[ATTN_ITEMS * 128];

// ---- ptx helpers ----
__device__ __forceinline__ void mma_f16(float* d, const uint32_t* a,
                                        const uint32_t* b, const float* c) {
    asm volatile(
        "mma.sync.aligned.m16n8k16.row.col.f32.f16.f16.f32 "
        "{%0,%1,%2,%3},{%4,%5,%6,%7},{%8,%9},{%10,%11,%12,%13};"
        : "=f"(d[0]), "=f"(d[1]), "=f"(d[2]), "=f"(d[3])
        : "r"(a[0]), "r"(a[1]), "r"(a[2]), "r"(a[3]),
          "r"(b[0]), "r"(b[1]),
          "f"(c[0]), "f"(c[1]), "f"(c[2]), "f"(c[3]));
}
__device__ __forceinline__ void mma_h16(uint32_t* d, const uint32_t* a,
                                        const uint32_t* b, const uint32_t* c) {
    asm volatile(
        "mma.sync.aligned.m16n8k16.row.col.f16.f16.f16.f16 "
        "{%0,%1},{%2,%3,%4,%5},{%6,%7},{%8,%9};"
        : "=r"(d[0]), "=r"(d[1])
        : "r"(a[0]), "r"(a[1]), "r"(a[2]), "r"(a[3]),
          "r"(b[0]), "r"(b[1]), "r"(c[0]), "r"(c[1]));
}
__device__ __forceinline__ void ldsm4(uint32_t* r, uint32_t a) {
    asm volatile("ldmatrix.sync.aligned.m8n8.x4.shared.b16 {%0,%1,%2,%3}, [%4];"
                 : "=r"(r[0]), "=r"(r[1]), "=r"(r[2]), "=r"(r[3]) : "r"(a));
}
__device__ __forceinline__ void ldsm4t(uint32_t* r, uint32_t a) {
    asm volatile("ldmatrix.sync.aligned.m8n8.x4.trans.shared.b16 {%0,%1,%2,%3}, [%4];"
                 : "=r"(r[0]), "=r"(r[1]), "=r"(r[2]), "=r"(r[3]) : "r"(a));
}
__device__ __forceinline__ void cpa16(uint32_t dst, const void* src) {
    asm volatile("cp.async.cg.shared.global [%0], [%1], 16;\n" :: "r"(dst), "l"(src));
}
#define CP_COMMIT() asm volatile("cp.async.commit_group;\n" ::: "memory")
#define CP_WAIT1()  asm volatile("cp.async.wait_group 1;\n" ::: "memory")
#define CP_WAIT0()  asm volatile("cp.async.wait_group 0;\n" ::: "memory")

__device__ __forceinline__ uint32_t h2u(half2 h) { return *(uint32_t*)&h; }
__device__ __forceinline__ half2 u2h(uint32_t u) { return *(half2*)&u; }
__device__ __forceinline__ uint32_t ex2h2(uint32_t x) {
    uint32_t r;
    asm("ex2.approx.f16x2 %0, %1;" : "=r"(r) : "r"(x));
    return r;
}

constexpr float SC_ = 0.125f * 1.44269504088896341f;

// ============================================================
// fused fp32 -> fp16 conversion for all 4 weight matrices
// ============================================================
constexpr int N8_QKV = QKVD * C_ / 8;
constexpr int N8_PRJ = C_ * C_ / 8;
constexpr int N8_FC  = 4 * C_ * C_ / 8;
constexpr int N8_TOT = N8_QKV + N8_PRJ + 2 * N8_FC;

__global__ void f2h_all(const float* __restrict__ s0, const float* __restrict__ s1,
                        const float* __restrict__ s2, const float* __restrict__ s3,
                        __half* __restrict__ d0, __half* __restrict__ d1,
                        __half* __restrict__ d2, __half* __restrict__ d3) {
    int i = blockIdx.x * blockDim.x + threadIdx.x;
    if (i >= N8_TOT) return;
    const float* s; __half* d;
    if (i < N8_QKV)                       { s = s0; d = d0; }
    else if (i < N8_QKV + N8_PRJ)         { s = s1; d = d1; i -= N8_QKV; }
    else if (i < N8_QKV + N8_PRJ + N8_FC) { s = s2; d = d2; i -= N8_QKV + N8_PRJ; }
    else                                  { s = s3; d = d3; i -= N8_QKV + N8_PRJ + N8_FC; }
    const float4* sp = (const float4*)s;
    float4 a = sp[2 * i], b = sp[2 * i + 1];
    half2 h[4] = {__floats2half2_rn(a.x, a.y), __floats2half2_rn(a.z, a.w),
                  __floats2half2_rn(b.x, b.y), __floats2half2_rn(b.z, b.w)};
    ((uint4*)d)[i] = *(uint4*)h;
}

// ============================================================
// LayerNorm: one WARP per row. Also resets attn counter.
// ============================================================
__global__ void ln_h(const float* __restrict__ x, const float* __restrict__ g,
                     const float* __restrict__ b, __half* __restrict__ out) {
    const int lane = threadIdx.x & 31;
    const int row = blockIdx.x * 8 + (threadIdx.x >> 5);
    if (row == 0 && lane == 0) g_attn_ctr = 0;

    const float2* xr = (const float2*)(x + (size_t)row * C_);
    float2 v[12];
    float s = 0.f, sq = 0.f;
#pragma unroll
    for (int j = 0; j < 12; j++) {
        v[j] = xr[lane + j * 32];
        s += v[j].x + v[j].y;
        sq += v[j].x * v[j].x + v[j].y * v[j].y;
    }
#pragma unroll
    for (int o = 16; o > 0; o >>= 1) {
        s  += __shfl_xor_sync(0xffffffffu, s, o);
        sq += __shfl_xor_sync(0xffffffffu, sq, o);
    }
    float mean = s * (1.0f / C_);
    float rstd = rsqrtf(sq * (1.0f / C_) - mean * mean + 1e-5f);
    half2* orow = (half2*)(out + (size_t)row * C_);
    const float2* gp = (const float2*)g;
    const float2* bp = (const float2*)b;
#pragma unroll
    for (int j = 0; j < 12; j++) {
        float2 gg = gp[lane + j * 32];
        float2 bb = bp[lane + j * 32];
        orow[lane + j * 32] = __floats2half2_rn(
            (v[j].x - mean) * rstd * gg.x + bb.x,
            (v[j].y - mean) * rstd * gg.y + bb.y);
    }
}

// ============================================================
// fp16 tensor-core GEMM NT: 128x128x32 block, 4 warps (2x2),
// warp tile 64x64, 3-stage cp.async, 2 blocks/SM.  (R11-proven)
// ============================================================
constexpr int ASTR = 40;
constexpr int A_STG = 128 * ASTR;
constexpr int SMEM_GEMM = 3 * 2 * A_STG * 2;   // 61440 bytes

template <int ACT, int OUTH, int ROPE>
__global__ void __launch_bounds__(128, 2)
gemm_h(const __half* __restrict__ A, const __half* __restrict__ W,
       const float* __restrict__ bias, const float* __restrict__ resid,
       void* __restrict__ Cout, int M, int Nd, int K,
       const float* __restrict__ cx, const float* __restrict__ sx,
       const float* __restrict__ cy, const float* __restrict__ sy)
{
    extern __shared__ __half sm[];
    __half* As = sm;
    __half* Ws = sm + 3 * A_STG;

    const int tid = threadIdx.x, lane = tid & 31, wid = tid >> 5;
    const int warpM = wid >> 1, warpN = wid & 1;
    const int g = lane >> 2, q = lane & 3;
    const int m0 = blockIdx.y * 128, n0 = blockIdx.x * 128;

    const uint32_t asbase = (uint32_t)__cvta_generic_to_shared(As);
    const uint32_t wsbase = (uint32_t)__cvta_generic_to_shared(Ws);

    auto stage = [&](int t, int s) {
        int k0 = t * 32;
        uint32_t ab = asbase + s * (A_STG * 2);
        uint32_t wb = wsbase + s * (A_STG * 2);
#pragma unroll
        for (int i = 0; i < 4; i++) {
            int idx = tid + i * 128;
            int r = idx >> 2, c = (idx & 3) * 8;
            cpa16(ab + (r * ASTR + c) * 2, A + (size_t)(m0 + r) * K + k0 + c);
            cpa16(wb + (r * ASTR + c) * 2, W + (size_t)(n0 + r) * K + k0 + c);
        }
    };

    float acc[4][8][4];
#pragma unroll
    for (int mt = 0; mt < 4; mt++)
#pragma unroll
        for (int nt = 0; nt < 8; nt++)
#pragma unroll
            for (int r = 0; r < 4; r++) acc[mt][nt][r] = 0.f;

    const int T = K / 32;
    stage(0, 0); CP_COMMIT();
    stage(1, 1); CP_COMMIT();

    const int lrow = warpM * 64 + (lane & 7) + ((lane >> 3) & 1) * 8;
    const int lcol = (lane >> 4) * 8;
    const int brow = (lane & 7) + ((lane >> 4) & 1) * 8;
    const int bcol = ((lane >> 3) & 1) * 8;

    for (int t = 0; t < T; t++) {
        CP_WAIT1();
        __syncthreads();
        if (t + 2 < T) stage(t + 2, (t + 2) % 3);
        CP_COMMIT();
        const int s = t % 3;
        const uint32_t ab = asbase + s * (A_STG * 2);
        const uint32_t wb = wsbase + s * (A_STG * 2);
#pragma unroll
        for (int kk = 0; kk < 32; kk += 16) {
            uint32_t af[4][4];
#pragma unroll
            for (int mt = 0; mt < 4; mt++)
                ldsm4(af[mt], ab + ((lrow + mt * 16) * ASTR + lcol + kk) * 2);
            uint32_t bf[8][2];
#pragma unroll
            for (int ntp = 0; ntp < 4; ntp++) {
                uint32_t r[4];
                ldsm4(r, wb + ((warpN * 64 + ntp * 16 + brow) * ASTR + kk + bcol) * 2);
                bf[2 * ntp][0] = r[0]; bf[2 * ntp][1] = r[1];
                bf[2 * ntp + 1][0] = r[2]; bf[2 * ntp + 1][1] = r[3];
            }
#pragma unroll
            for (int mt = 0; mt < 4; mt++)
#pragma unroll
                for (int nt = 0; nt < 8; nt++)
                    mma_f16(acc[mt][nt], af[mt], bf[nt], acc[mt][nt]);
        }
    }

    if (ROPE) {
        __half* O = (__half*)Cout;
        const int chunk = n0 + warpN * 64;
        const bool qk = chunk < 2 * C_;
#pragma unroll
        for (int mt = 0; mt < 4; mt++) {
            int m = m0 + warpM * 64 + mt * 16 + g;
            int ntok = m % N_;
            if (qk) {
#pragma unroll
                for (int base = 0; base < 8; base += 4) {
                    const float* ct = base ? cx : cy;
                    const float* st = base ? sx : sy;
#pragma unroll
                    for (int p = 0; p < 2; p++) {
                        int j = p * 8 + 2 * q;
                        float2 c0 = *(const float2*)&ct[ntok * 32 + j];
                        float2 s0 = *(const float2*)&st[ntok * 32 + j];
                        float2 c1 = *(const float2*)&ct[(ntok + 8) * 32 + j];
                        float2 s1 = *(const float2*)&st[(ntok + 8) * 32 + j];
                        float* lo = acc[mt][base + p];
                        float* hi = acc[mt][base + p + 2];
                        float t1, t2;
                        t1 = lo[0]; t2 = hi[0];
                        lo[0] = t1 * c0.x - t2 * s0.x; hi[0] = t2 * c0.x + t1 * s0.x;
                        t1 = lo[1]; t2 = hi[1];
                        lo[1] = t1 * c0.y - t2 * s0.y; hi[1] = t2 * c0.y + t1 * s0.y;
                        t1 = lo[2]; t2 = hi[2];
                        lo[2] = t1 * c1.x - t2 * s1.x; hi[2] = t2 * c1.x + t1 * s1.x;
                        t1 = lo[3]; t2 = hi[3];
                        lo[3] = t1 * c1.y - t2 * s1.y; hi[3] = t2 * c1.y + t1 * s1.y;
                    }
                }
            }
#pragma unroll
            for (int nt = 0; nt < 8; nt++) {
                int c = chunk + nt * 8 + 2 * q;
                size_t i0 = (size_t)m * Nd + c, i1 = (size_t)(m + 8) * Nd + c;
                *(half2*)(O + i0) = __floats2half2_rn(acc[mt][nt][0], acc[mt][nt][1]);
                *(half2*)(O + i1) = __floats2half2_rn(acc[mt][nt][2], acc[mt][nt][3]);
            }
        }
        return;
    }

#pragma unroll
    for (int mt = 0; mt < 4; mt++) {
#pragma unroll
        for (int nt = 0; nt < 8; nt++) {
            int m = m0 + warpM * 64 + mt * 16 + g;
            int c = n0 + warpN * 64 + nt * 8 + 2 * q;
            float bv0 = bias ? bias[c] : 0.f;
            float bv1 = bias ? bias[c + 1] : 0.f;
            float v0 = acc[mt][nt][0] + bv0, v1 = acc[mt][nt][1] + bv1;
            float v2 = acc[mt][nt][2] + bv0, v3 = acc[mt][nt][3] + bv1;
            if (ACT == 1) {
                v0 = 0.5f * v0 * (1.0f + erff(v0 * 0.70710678118654752f));
                v1 = 0.5f * v1 * (1.0f + erff(v1 * 0.70710678118654752f));
                v2 = 0.5f * v2 * (1.0f + erff(v2 * 0.70710678118654752f));
                v3 = 0.5f * v3 * (1.0f + erff(v3 * 0.70710678118654752f));
            }
            size_t i0 = (size_t)m * Nd + c, i1 = (size_t)(m + 8) * Nd + c;
            if (OUTH) {
                __half* O = (__half*)Cout;
                *(half2*)(O + i0) = __floats2half2_rn(v0, v1);
                *(half2*)(O + i1) = __floats2half2_rn(v2, v3);
            } else {
                float* O = (float*)Cout;
                if (resid) {
                    float2 r0 = *(const float2*)&resid[i0];
                    float2 r1 = *(const float2*)&resid[i1];
                    v0 += r0.x; v1 += r0.y; v2 += r1.x; v3 += r1.y;
                }
                *(float2*)&O[i0] = make_float2(v0, v1);
                *(float2*)&O[i1] = make_float2(v2, v3);
            }
        }
    }
}

// ============================================================
// Flash attention, persistent work-stealing, SPLIT-KV:
// item = (bh, qb, kvhalf); 1152 items; each covers 1536 keys.
// Writes normalized partial O (half) + per-row m,l (fp32).
// ============================================================
constexpr int KSTR = 72;
constexpr int Q_OFF = 0;
constexpr int K_OFF = 128 * KSTR;
constexpr int V_OFF = K_OFF + 3 * 64 * KSTR;
constexpr int SMEM_ATTN = (V_OFF + 3 * 64 * KSTR) * 2;  // 73728 bytes

__global__ void __launch_bounds__(128, 3)
attn_h(const __half* __restrict__ qkvh)
{
    extern __shared__ __half smA[];
    __shared__ int s_idx;

    const int tid = threadIdx.x, lane = tid & 31, wid = tid >> 5;
    const int g = lane >> 2, q = lane & 3;

    const uint32_t base = (uint32_t)__cvta_generic_to_shared(smA);
    const uint32_t qsb = base + Q_OFF * 2;
    const uint32_t ksb = base + K_OFF * 2;
    const uint32_t vsb = base + V_OFF * 2;

    const int qlrow = wid * 32 + (lane & 7) + ((lane >> 3) & 1) * 8;
    const int qlcol = (lane >> 4) * 8;
    const int brow = (lane & 7) + ((lane >> 4) & 1) * 8;
    const int bcol = ((lane >> 3) & 1) * 8;
    const int vrow = (lane & 7) + ((lane >> 3) & 1) * 8;
    const int vcol = ((lane >> 4) & 1) * 8;

    const half2 sc2 = __float2half2_rn(SC_);
    const uint32_t ones2[2] = {0x3C003C00u, 0x3C003C00u};
    constexpr int T = 24;   // 1536 keys per item

    for (;;) {
        if (tid == 0) s_idx = atomicAdd(&g_attn_ctr, 1);
        __syncthreads();
        const int item = s_idx;
        if (item >= ATTN_ITEMS) break;
        const int bh = item / 48;
        const int rest = item % 48;
        const int qb = rest >> 1;
        const int kvh = rest & 1;
        const int b = bh / H_, h = bh % H_;
        const int kt0 = kvh * 1536;

        const size_t qgbase = ((size_t)(b * N_ + qb * 128)) * QKVD + h * HD_;
        const size_t kgbase = (size_t)(b * N_) * QKVD + C_ + h * HD_;
        const size_t vgbase = kgbase + C_;

        auto stage = [&](int kt, int buf) {
#pragma unroll
            for (int i = 0; i < 4; i++) {
                int idx = tid + i * 128;
                int r = idx >> 3, c = idx & 7;
                size_t roff = (size_t)(kt + r) * QKVD + c * 8;
                cpa16(ksb + (buf * 64 * KSTR + r * KSTR + c * 8) * 2, qkvh + kgbase + roff);
                cpa16(vsb + (buf * 64 * KSTR + r * KSTR + c * 8) * 2, qkvh + vgbase + roff);
            }
            CP_COMMIT();
        };

#pragma unroll
        for (int i = 0; i < 8; i++) {
            int idx = tid + i * 128;
            int r = idx >> 3, c = idx & 7;
            cpa16(qsb + (r * KSTR + c * 8) * 2, qkvh + qgbase + (size_t)r * QKVD + c * 8);
        }
        stage(kt0, 0);
        stage(kt0 + 64, 1);

        float o[2][8][4];
#pragma unroll
        for (int mt = 0; mt < 2; mt++)
#pragma unroll
            for (int nt = 0; nt < 8; nt++)
#pragma unroll
                for (int r = 0; r < 4; r++) o[mt][nt][r] = 0.f;
        float mv[2][2] = {{-1e30f, -1e30f}, {-1e30f, -1e30f}};
        float lv[2][2] = {{0.f, 0.f}, {0.f, 0.f}};

        for (int t = 0; t < T; t++) {
            if (t + 1 < T) CP_WAIT1(); else CP_WAIT0();
            __syncthreads();
            if (t + 2 < T) stage(kt0 + (t + 2) * 64, (t + 2) % 3);

            const uint32_t kb = ksb + (t % 3) * (64 * KSTR * 2);
            const uint32_t vb = vsb + (t % 3) * (64 * KSTR * 2);

            uint32_t s[2][8][2];
#pragma unroll
            for (int mt = 0; mt < 2; mt++)
#pragma unroll
                for (int nt = 0; nt < 8; nt++) { s[mt][nt][0] = 0u; s[mt][nt][1] = 0u; }
#pragma unroll
            for (int ks = 0; ks < 4; ks++) {
                uint32_t aq[2][4];
#pragma unroll
                for (int mt = 0; mt < 2; mt++)
                    ldsm4(aq[mt], qsb + ((qlrow + mt * 16) * KSTR + ks * 16 + qlcol) * 2);
#pragma unroll
                for (int ntp = 0; ntp < 4; ntp++) {
                    uint32_t r[4];
                    ldsm4(r, kb + ((ntp * 16 + brow) * KSTR + ks * 16 + bcol) * 2);
#pragma unroll
                    for (int mt = 0; mt < 2; mt++) {
                        mma_h16(s[mt][2 * ntp],     aq[mt], r,     s[mt][2 * ntp]);
                        mma_h16(s[mt][2 * ntp + 1], aq[mt], r + 2, s[mt][2 * ntp + 1]);
                    }
                }
            }

            float al[2][2];
#pragma unroll
            for (int mt = 0; mt < 2; mt++) {
                half2 hx0 = u2h(s[mt][0][0]), hx1 = u2h(s[mt][0][1]);
#pragma unroll
                for (int nt = 1; nt < 8; nt++) {
                    hx0 = __hmax2(hx0, u2h(s[mt][nt][0]));
                    hx1 = __hmax2(hx1, u2h(s[mt][nt][1]));
                }
                float mx0 = fmaxf(__low2float(hx0), __high2float(hx0));
                float mx1 = fmaxf(__low2float(hx1), __high2float(hx1));
                mx0 = fmaxf(mx0, __shfl_xor_sync(0xffffffffu, mx0, 1));
                mx0 = fmaxf(mx0, __shfl_xor_sync(0xffffffffu, mx0, 2));
                mx1 = fmaxf(mx1, __shfl_xor_sync(0xffffffffu, mx1, 1));
                mx1 = fmaxf(mx1, __shfl_xor_sync(0xffffffffu, mx1, 2));

                float nm0 = fmaxf(mv[mt][0], mx0), nm1 = fmaxf(mv[mt][1], mx1);
                float a0 = exp2f((mv[mt][0] - nm0) * SC_);
                float a1 = exp2f((mv[mt][1] - nm1) * SC_);
                mv[mt][0] = nm0; mv[mt][1] = nm1;
                al[mt][0] = a0; al[mt][1] = a1;

                if (!__all_sync(0xffffffffu, (a0 == 1.f) & (a1 == 1.f))) {
#pragma unroll
                    for (int nt = 0; nt < 8; nt++) {
                        o[mt][nt][0] *= a0; o[mt][nt][1] *= a0;
                        o[mt][nt][2] *= a1; o[mt][nt][3] *= a1;
                    }
                }
                half2 nm02 = __float2half2_rn(nm0);
                half2 nm12 = __float2half2_rn(nm1);
#pragma unroll
                for (int nt = 0; nt < 8; nt++) {
                    s[mt][nt][0] = ex2h2(h2u(__hmul2(__hsub2(u2h(s[mt][nt][0]), nm02), sc2)));
                    s[mt][nt][1] = ex2h2(h2u(__hmul2(__hsub2(u2h(s[mt][nt][1]), nm12), sc2)));
                }
            }

            float fs[2][4] = {{0.f, 0.f, 0.f, 0.f}, {0.f, 0.f, 0.f, 0.f}};
#pragma unroll
            for (int k2 = 0; k2 < 4; k2++) {
                uint32_t af[2][4];
#pragma unroll
                for (int mt = 0; mt < 2; mt++) {
                    af[mt][0] = s[mt][2 * k2][0];     af[mt][1] = s[mt][2 * k2][1];
                    af[mt][2] = s[mt][2 * k2 + 1][0]; af[mt][3] = s[mt][2 * k2 + 1][1];
                    mma_f16(fs[mt], af[mt], ones2, fs[mt]);
                }
#pragma unroll
                for (int ntp = 0; ntp < 4; ntp++) {
                    uint32_t r[4];
                    ldsm4t(r, vb + ((k2 * 16 + vrow) * KSTR + ntp * 16 + vcol) * 2);
#pragma unroll
                    for (int mt = 0; mt < 2; mt++) {
                        mma_f16(o[mt][2 * ntp],     af[mt], r,     o[mt][2 * ntp]);
                        mma_f16(o[mt][2 * ntp + 1], af[mt], r + 2, o[mt][2 * ntp + 1]);
                    }
                }
            }
#pragma unroll
            for (int mt = 0; mt < 2; mt++) {
                lv[mt][0] = lv[mt][0] * al[mt][0] + fs[mt][0];
                lv[mt][1] = lv[mt][1] * al[mt][1] + fs[mt][2];
            }
        }

        // write normalized partials + (m,l)
        __half* po = g_po + (size_t)item * (128 * 64);
#pragma unroll
        for (int mt = 0; mt < 2; mt++) {
            int rr = wid * 32 + mt * 16 + g;      // row within item (and rr+8)
            float inv0 = 1.f / lv[mt][0], inv1 = 1.f / lv[mt][1];
            __half* p0 = po + rr * 64;
            __half* p1 = po + (rr + 8) * 64;
#pragma unroll
            for (int nt = 0; nt < 8; nt++) {
                int c = nt * 8 + 2 * q;
                *(half2*)(p0 + c) = __floats2half2_rn(o[mt][nt][0] * inv0, o[mt][nt][1] * inv0);
                *(half2*)(p1 + c) = __floats2half2_rn(o[mt][nt][2] * inv1, o[mt][nt][3] * inv1);
            }
            if (q == 0) {
                g_pm[item * 128 + rr] = mv[mt][0];
                g_pl[item * 128 + rr] = lv[mt][0];
                g_pm[item * 128 + rr + 8] = mv[mt][1];
                g_pl[item * 128 + rr + 8] = lv[mt][1];
            }
        }
    }
}

// ============================================================
// Merge the two KV-half partials. One warp per output row.
// ============================================================
__global__ void attn_merge(__half* __restrict__ outh) {
    int w = (blockIdx.x * blockDim.x + threadIdx.x) >> 5;   // 0 .. 576*128-1
    int lane = threadIdx.x & 31;
    int r = w & 127;
    int it2 = w >> 7;                 // bh*24 + qb
    int bh = it2 / 24, qb = it2 % 24;
    int b = bh / H_, h = bh % H_;
    int i1 = it2 * 2, i2 = i1 + 1;

    float m1 = g_pm[i1 * 128 + r], l1 = g_pl[i1 * 128 + r];
    float m2 = g_pm[i2 * 128 + r], l2 = g_pl[i2 * 128 + r];
    float ms = fmaxf(m1, m2);
    float w1 = l1 * exp2f((m1 - ms) * SC_);
    float w2 = l2 * exp2f((m2 - ms) * SC_);
    float inv = 1.f / (w1 + w2);
    w1 *= inv; w2 *= inv;

    half2 a = ((const half2*)(g_po + (size_t)i1 * (128 * 64) + r * 64))[lane];
    half2 c = ((const half2*)(g_po + (size_t)i2 * (128 * 64) + r * 64))[lane];
    float o0 = __low2float(a) * w1 + __low2float(c) * w2;
    float o1 = __high2float(a) * w1 + __high2float(c) * w2;

    int n = qb * 128 + r;
    ((half2*)(outh + (size_t)(b * N_ + n) * C_ + h * HD_))[lane] = __floats2half2_rn(o0, o1);
}

// ============================================================
// Launch orchestration
// ============================================================
extern "C" void kernel_launch(void* const* d_in, const int* in_sizes, int n_in,
                              void* d_out, int out_size) {
    const float* x      = (const float*)d_in[0];
    const float* w_qkv  = (const float*)d_in[1];
    const float* w_proj = (const float*)d_in[2];
    const float* b_proj = (const float*)d_in[3];
    const float* g1     = (const float*)d_in[4];
    const float* beta1  = (const float*)d_in[5];
    const float* g2     = (const float*)d_in[6];
    const float* beta2  = (const float*)d_in[7];
    const float* w_fc1  = (const float*)d_in[8];
    const float* b_fc1  = (const float*)d_in[9];
    const float* w_fc2  = (const float*)d_in[10];
    const float* b_fc2  = (const float*)d_in[11];
    const float* cos_x  = (const float*)d_in[12];
    const float* sin_x  = (const float*)d_in[13];
    const float* cos_y  = (const float*)d_in[14];
    const float* sin_y  = (const float*)d_in[15];
    float* out = (float*)d_out;

    __half *xnh, *qkvh, *attnh, *hh, *wqkvh, *wprojh, *wfc1h, *wfc2h;
    float* x1;
    cudaGetSymbolAddress((void**)&xnh,   g_xnh);
    cudaGetSymbolAddress((void**)&qkvh,  g_qkvh);
    cudaGetSymbolAddress((void**)&attnh, g_attnh);
    cudaGetSymbolAddress((void**)&x1,    g_x1);
    cudaGetSymbolAddress((void**)&hh,    g_hh);
    cudaGetSymbolAddress((void**)&wqkvh, g_wqkvh);
    cudaGetSymbolAddress((void**)&wprojh, g_wprojh);
    cudaGetSymbolAddress((void**)&wfc1h, g_wfc1h);
    cudaGetSymbolAddress((void**)&wfc2h, g_wfc2h);

    cudaFuncSetAttribute(gemm_h<0, 1, 1>, cudaFuncAttributeMaxDynamicSharedMemorySize, SMEM_GEMM);
    cudaFuncSetAttribute(gemm_h<0, 0, 0>, cudaFuncAttributeMaxDynamicSharedMemorySize, SMEM_GEMM);
    cudaFuncSetAttribute(gemm_h<1, 1, 0>, cudaFuncAttributeMaxDynamicSharedMemorySize, SMEM_GEMM);
    cudaFuncSetAttribute(attn_h, cudaFuncAttributeMaxDynamicSharedMemorySize, SMEM_ATTN);

    // weight conversions (single launch)
    f2h_all<<<(N8_TOT + 255) / 256, 256>>>(w_qkv, w_proj, w_fc1, w_fc2,
                                           wqkvh, wprojh, wfc1h, wfc2h);

    // 1. LN1 -> half (also zeroes the attn work counter)
    ln_h<<<M_ / 8, 256>>>(x, g1, beta1, xnh);
    // 2. QKV projection + fused 2D RoPE -> half
    gemm_h<0, 1, 1><<<dim3(QKVD / 128, M_ / 128), 128, SMEM_GEMM>>>(
        xnh, wqkvh, nullptr, nullptr, qkvh, M_, QKVD, C_, cos_x, sin_x, cos_y, sin_y);
    // 3. Attention partials (persistent, work-stealing, split-KV)
    attn_h<<<456, 128, SMEM_ATTN>>>(qkvh);
    // 3b. Merge KV-half partials -> attnh
    attn_merge<<<(576 * 128 * 32) / 256, 256>>>(attnh);
    // 4. proj + bias + residual(x) -> x1 (fp32)
    gemm_h<0, 0, 0><<<dim3(C_ / 128, M_ / 128), 128, SMEM_GEMM>>>(
        attnh, wprojh, b_proj, x, x1, M_, C_, C_, nullptr, nullptr, nullptr, nullptr);
    // 5. LN2 -> half
    ln_h<<<M_ / 8, 256>>>(x1, g2, beta2, xnh);
    // 6. FC1 + bias + GELU -> half
    gemm_h<1, 1, 0><<<dim3(4 * C_ / 128, M_ / 128), 128, SMEM_GEMM>>>(
        xnh, wfc1h, b_fc1, nullptr, hh, M_, 4 * C_, C_, nullptr, nullptr, nullptr, nullptr);
    // 7. FC2 + bias + residual(x1) -> out (fp32)
    gemm_h<0, 0, 0><<<dim3(C_ / 128, M_ / 128), 128, SMEM_GEMM>>>(
        hh, wfc2h, b_fc2, x1, out, M_, C_, 4 * C_, nullptr, nullptr, nullptr, nullptr);
}

// round 15
// speedup vs baseline: 1.0480x; 1.0216x over previous
#include <cuda_runtime.h>
#include <cuda_fp16.h>
#include <cstdint>
#include <cstddef>

constexpr int B_ = 2, N_ = 3072, C_ = 768, H_ = 12, HD_ = 64;
constexpr int M_ = B_ * N_;           // 6144
constexpr int QKVD = 3 * C_;          // 2304

// ---- static scratch ----
__device__ __half g_xnh[M_ * C_];
__device__ __half g_qkvh[(size_t)M_ * QKVD];
__device__ __half g_attnh[M_ * C_];
__device__ float  g_x1[M_ * C_];
__device__ __half g_hh[(size_t)M_ * 4 * C_];
__device__ __half g_wqkvh[QKVD * C_];
__device__ __half g_wprojh[C_ * C_];
__device__ __half g_wfc1h[4 * C_ * C_];
__device__ __half g_wfc2h[C_ * 4 * C_];
__device__ int    g_attn_ctr;

// ---- ptx helpers ----
__device__ __forceinline__ void mma_f16(float* d, const uint32_t* a,
                                        const uint32_t* b, const float* c) {
    asm volatile(
        "mma.sync.aligned.m16n8k16.row.col.f32.f16.f16.f32 "
        "{%0,%1,%2,%3},{%4,%5,%6,%7},{%8,%9},{%10,%11,%12,%13};"
        : "=f"(d[0]), "=f"(d[1]), "=f"(d[2]), "=f"(d[3])
        : "r"(a[0]), "r"(a[1]), "r"(a[2]), "r"(a[3]),
          "r"(b[0]), "r"(b[1]),
          "f"(c[0]), "f"(c[1]), "f"(c[2]), "f"(c[3]));
}
// fp16 accumulator variant (2 output regs)
__device__ __forceinline__ void mma_h16(uint32_t* d, const uint32_t* a,
                                        const uint32_t* b, const uint32_t* c) {
    asm volatile(
        "mma.sync.aligned.m16n8k16.row.col.f16.f16.f16.f16 "
        "{%0,%1},{%2,%3,%4,%5},{%6,%7},{%8,%9};"
        : "=r"(d[0]), "=r"(d[1])
        : "r"(a[0]), "r"(a[1]), "r"(a[2]), "r"(a[3]),
          "r"(b[0]), "r"(b[1]), "r"(c[0]), "r"(c[1]));
}
__device__ __forceinline__ void ldsm4(uint32_t* r, uint32_t a) {
    asm volatile("ldmatrix.sync.aligned.m8n8.x4.shared.b16 {%0,%1,%2,%3}, [%4];"
                 : "=r"(r[0]), "=r"(r[1]), "=r"(r[2]), "=r"(r[3]) : "r"(a));
}
__device__ __forceinline__ void ldsm4t(uint32_t* r, uint32_t a) {
    asm volatile("ldmatrix.sync.aligned.m8n8.x4.trans.shared.b16 {%0,%1,%2,%3}, [%4];"
                 : "=r"(r[0]), "=r"(r[1]), "=r"(r[2]), "=r"(r[3]) : "r"(a));
}
__device__ __forceinline__ void cpa16(uint32_t dst, const void* src) {
    asm volatile("cp.async.cg.shared.global [%0], [%1], 16;\n" :: "r"(dst), "l"(src));
}
#define CP_COMMIT() asm volatile("cp.async.commit_group;\n" ::: "memory")
#define CP_WAIT1()  asm volatile("cp.async.wait_group 1;\n" ::: "memory")
#define CP_WAIT0()  asm volatile("cp.async.wait_group 0;\n" ::: "memory")

__device__ __forceinline__ uint32_t h2u(half2 h) { return *(uint32_t*)&h; }
__device__ __forceinline__ half2 u2h(uint32_t u) { return *(half2*)&u; }
__device__ __forceinline__ uint32_t ex2h2(uint32_t x) {
    uint32_t r;
    asm("ex2.approx.f16x2 %0, %1;" : "=r"(r) : "r"(x));
    return r;
}

constexpr float SC_ = 0.125f * 1.44269504088896341f;

// ============================================================
// fused fp32 -> fp16 conversion for all 4 weight matrices
// ============================================================
constexpr int N8_QKV = QKVD * C_ / 8;
constexpr int N8_PRJ = C_ * C_ / 8;
constexpr int N8_FC  = 4 * C_ * C_ / 8;
constexpr int N8_TOT = N8_QKV + N8_PRJ + 2 * N8_FC;

__global__ void f2h_all(const float* __restrict__ s0, const float* __restrict__ s1,
                        const float* __restrict__ s2, const float* __restrict__ s3,
                        __half* __restrict__ d0, __half* __restrict__ d1,
                        __half* __restrict__ d2, __half* __restrict__ d3) {
    int i = blockIdx.x * blockDim.x + threadIdx.x;
    if (i >= N8_TOT) return;
    const float* s; __half* d;
    if (i < N8_QKV)                       { s = s0; d = d0; }
    else if (i < N8_QKV + N8_PRJ)         { s = s1; d = d1; i -= N8_QKV; }
    else if (i < N8_QKV + N8_PRJ + N8_FC) { s = s2; d = d2; i -= N8_QKV + N8_PRJ; }
    else                                  { s = s3; d = d3; i -= N8_QKV + N8_PRJ + N8_FC; }
    const float4* sp = (const float4*)s;
    float4 a = sp[2 * i], b = sp[2 * i + 1];
    half2 h[4] = {__floats2half2_rn(a.x, a.y), __floats2half2_rn(a.z, a.w),
                  __floats2half2_rn(b.x, b.y), __floats2half2_rn(b.z, b.w)};
    ((uint4*)d)[i] = *(uint4*)h;
}

// ============================================================
// LayerNorm: one WARP per row. Also resets attn counter.
// ============================================================
__global__ void ln_h(const float* __restrict__ x, const float* __restrict__ g,
                     const float* __restrict__ b, __half* __restrict__ out) {
    const int lane = threadIdx.x & 31;
    const int row = blockIdx.x * 8 + (threadIdx.x >> 5);
    if (row == 0 && lane == 0) g_attn_ctr = 0;

    const float2* xr = (const float2*)(x + (size_t)row * C_);
    float2 v[12];
    float s = 0.f, sq = 0.f;
#pragma unroll
    for (int j = 0; j < 12; j++) {
        v[j] = xr[lane + j * 32];
        s += v[j].x + v[j].y;
        sq += v[j].x * v[j].x + v[j].y * v[j].y;
    }
#pragma unroll
    for (int o = 16; o > 0; o >>= 1) {
        s  += __shfl_xor_sync(0xffffffffu, s, o);
        sq += __shfl_xor_sync(0xffffffffu, sq, o);
    }
    float mean = s * (1.0f / C_);
    float rstd = rsqrtf(sq * (1.0f / C_) - mean * mean + 1e-5f);
    half2* orow = (half2*)(out + (size_t)row * C_);
    const float2* gp = (const float2*)g;
    const float2* bp = (const float2*)b;
#pragma unroll
    for (int j = 0; j < 12; j++) {
        float2 gg = gp[lane + j * 32];
        float2 bb = bp[lane + j * 32];
        orow[lane + j * 32] = __floats2half2_rn(
            (v[j].x - mean) * rstd * gg.x + bb.x,
            (v[j].y - mean) * rstd * gg.y + bb.y);
    }
}

// ============================================================
// fp16 tensor-core GEMM NT: 128x128x32 block, 4 warps (2x2),
// warp tile 64x64, 3-stage cp.async, 2 blocks/SM.  (R11-proven)
// ============================================================
constexpr int ASTR = 40;
constexpr int A_STG = 128 * ASTR;
constexpr int SMEM_GEMM = 3 * 2 * A_STG * 2;   // 61440 bytes

template <int ACT, int OUTH, int ROPE>
__global__ void __launch_bounds__(128, 2)
gemm_h(const __half* __restrict__ A, const __half* __restrict__ W,
       const float* __restrict__ bias, const float* __restrict__ resid,
       void* __restrict__ Cout, int M, int Nd, int K,
       const float* __restrict__ cx, const float* __restrict__ sx,
       const float* __restrict__ cy, const float* __restrict__ sy)
{
    extern __shared__ __half sm[];
    __half* As = sm;
    __half* Ws = sm + 3 * A_STG;

    const int tid = threadIdx.x, lane = tid & 31, wid = tid >> 5;
    const int warpM = wid >> 1, warpN = wid & 1;
    const int g = lane >> 2, q = lane & 3;
    const int m0 = blockIdx.y * 128, n0 = blockIdx.x * 128;

    const uint32_t asbase = (uint32_t)__cvta_generic_to_shared(As);
    const uint32_t wsbase = (uint32_t)__cvta_generic_to_shared(Ws);

    auto stage = [&](int t, int s) {
        int k0 = t * 32;
        uint32_t ab = asbase + s * (A_STG * 2);
        uint32_t wb = wsbase + s * (A_STG * 2);
#pragma unroll
        for (int i = 0; i < 4; i++) {
            int idx = tid + i * 128;
            int r = idx >> 2, c = (idx & 3) * 8;
            cpa16(ab + (r * ASTR + c) * 2, A + (size_t)(m0 + r) * K + k0 + c);
            cpa16(wb + (r * ASTR + c) * 2, W + (size_t)(n0 + r) * K + k0 + c);
        }
    };

    float acc[4][8][4];
#pragma unroll
    for (int mt = 0; mt < 4; mt++)
#pragma unroll
        for (int nt = 0; nt < 8; nt++)
#pragma unroll
            for (int r = 0; r < 4; r++) acc[mt][nt][r] = 0.f;

    const int T = K / 32;
    stage(0, 0); CP_COMMIT();
    stage(1, 1); CP_COMMIT();

    const int lrow = warpM * 64 + (lane & 7) + ((lane >> 3) & 1) * 8;
    const int lcol = (lane >> 4) * 8;
    const int brow = (lane & 7) + ((lane >> 4) & 1) * 8;
    const int bcol = ((lane >> 3) & 1) * 8;

    for (int t = 0; t < T; t++) {
        CP_WAIT1();
        __syncthreads();
        if (t + 2 < T) stage(t + 2, (t + 2) % 3);
        CP_COMMIT();
        const int s = t % 3;
        const uint32_t ab = asbase + s * (A_STG * 2);
        const uint32_t wb = wsbase + s * (A_STG * 2);
#pragma unroll
        for (int kk = 0; kk < 32; kk += 16) {
            uint32_t af[4][4];
#pragma unroll
            for (int mt = 0; mt < 4; mt++)
                ldsm4(af[mt], ab + ((lrow + mt * 16) * ASTR + lcol + kk) * 2);
            uint32_t bf[8][2];
#pragma unroll
            for (int ntp = 0; ntp < 4; ntp++) {
                uint32_t r[4];
                ldsm4(r, wb + ((warpN * 64 + ntp * 16 + brow) * ASTR + kk + bcol) * 2);
                bf[2 * ntp][0] = r[0]; bf[2 * ntp][1] = r[1];
                bf[2 * ntp + 1][0] = r[2]; bf[2 * ntp + 1][1] = r[3];
            }
#pragma unroll
            for (int mt = 0; mt < 4; mt++)
#pragma unroll
                for (int nt = 0; nt < 8; nt++)
                    mma_f16(acc[mt][nt], af[mt], bf[nt], acc[mt][nt]);
        }
    }

    if (ROPE) {
        __half* O = (__half*)Cout;
        const int chunk = n0 + warpN * 64;
        const bool qk = chunk < 2 * C_;
#pragma unroll
        for (int mt = 0; mt < 4; mt++) {
            int m = m0 + warpM * 64 + mt * 16 + g;
            int ntok = m % N_;
            if (qk) {
#pragma unroll
                for (int base = 0; base < 8; base += 4) {
                    const float* ct = base ? cx : cy;
                    const float* st = base ? sx : sy;
#pragma unroll
                    for (int p = 0; p < 2; p++) {
                        int j = p * 8 + 2 * q;
                        float2 c0 = *(const float2*)&ct[ntok * 32 + j];
                        float2 s0 = *(const float2*)&st[ntok * 32 + j];
                        float2 c1 = *(const float2*)&ct[(ntok + 8) * 32 + j];
                        float2 s1 = *(const float2*)&st[(ntok + 8) * 32 + j];
                        float* lo = acc[mt][base + p];
                        float* hi = acc[mt][base + p + 2];
                        float t1, t2;
                        t1 = lo[0]; t2 = hi[0];
                        lo[0] = t1 * c0.x - t2 * s0.x; hi[0] = t2 * c0.x + t1 * s0.x;
                        t1 = lo[1]; t2 = hi[1];
                        lo[1] = t1 * c0.y - t2 * s0.y; hi[1] = t2 * c0.y + t1 * s0.y;
                        t1 = lo[2]; t2 = hi[2];
                        lo[2] = t1 * c1.x - t2 * s1.x; hi[2] = t2 * c1.x + t1 * s1.x;
                        t1 = lo[3]; t2 = hi[3];
                        lo[3] = t1 * c1.y - t2 * s1.y; hi[3] = t2 * c1.y + t1 * s1.y;
                    }
                }
            }
#pragma unroll
            for (int nt = 0; nt < 8; nt++) {
                int c = chunk + nt * 8 + 2 * q;
                size_t i0 = (size_t)m * Nd + c, i1 = (size_t)(m + 8) * Nd + c;
                *(half2*)(O + i0) = __floats2half2_rn(acc[mt][nt][0], acc[mt][nt][1]);
                *(half2*)(O + i1) = __floats2half2_rn(acc[mt][nt][2], acc[mt][nt][3]);
            }
        }
        return;
    }

#pragma unroll
    for (int mt = 0; mt < 4; mt++) {
#pragma unroll
        for (int nt = 0; nt < 8; nt++) {
            int m = m0 + warpM * 64 + mt * 16 + g;
            int c = n0 + warpN * 64 + nt * 8 + 2 * q;
            float bv0 = bias ? bias[c] : 0.f;
            float bv1 = bias ? bias[c + 1] : 0.f;
            float v0 = acc[mt][nt][0] + bv0, v1 = acc[mt][nt][1] + bv1;
            float v2 = acc[mt][nt][2] + bv0, v3 = acc[mt][nt][3] + bv1;
            if (ACT == 1) {
                v0 = 0.5f * v0 * (1.0f + erff(v0 * 0.70710678118654752f));
                v1 = 0.5f * v1 * (1.0f + erff(v1 * 0.70710678118654752f));
                v2 = 0.5f * v2 * (1.0f + erff(v2 * 0.70710678118654752f));
                v3 = 0.5f * v3 * (1.0f + erff(v3 * 0.70710678118654752f));
            }
            size_t i0 = (size_t)m * Nd + c, i1 = (size_t)(m + 8) * Nd + c;
            if (OUTH) {
                __half* O = (__half*)Cout;
                *(half2*)(O + i0) = __floats2half2_rn(v0, v1);
                *(half2*)(O + i1) = __floats2half2_rn(v2, v3);
            } else {
                float* O = (float*)Cout;
                if (resid) {
                    float2 r0 = *(const float2*)&resid[i0];
                    float2 r1 = *(const float2*)&resid[i1];
                    v0 += r0.x; v1 += r0.y; v2 += r1.x; v3 += r1.y;
                }
                *(float2*)&O[i0] = make_float2(v0, v1);
                *(float2*)&O[i1] = make_float2(v2, v3);
            }
        }
    }
}

// ============================================================
// Flash attention, persistent work-stealing blocks. (R11-proven
// structure, direct output.) 4 warps/block, 32 q-rows per warp,
// Q staged in smem, S in fp16 accumulators, 3-stage K/V ring.
// Row-sum moved OFF the tensor pipe: pairwise HADD2 + quad shfl.
// ============================================================
constexpr int KSTR = 72;
constexpr int ATTN_ITEMS = B_ * H_ * (N_ / 128);   // 576
constexpr int Q_OFF = 0;
constexpr int K_OFF = 128 * KSTR;
constexpr int V_OFF = K_OFF + 3 * 64 * KSTR;
constexpr int SMEM_ATTN = (V_OFF + 3 * 64 * KSTR) * 2;  // 73728 bytes

__global__ void __launch_bounds__(128, 3)
attn_h(const __half* __restrict__ qkvh, __half* __restrict__ outh)
{
    extern __shared__ __half smA[];
    __shared__ int s_idx;

    const int tid = threadIdx.x, lane = tid & 31, wid = tid >> 5;
    const int g = lane >> 2, q = lane & 3;

    const uint32_t base = (uint32_t)__cvta_generic_to_shared(smA);
    const uint32_t qsb = base + Q_OFF * 2;
    const uint32_t ksb = base + K_OFF * 2;
    const uint32_t vsb = base + V_OFF * 2;

    const int qlrow = wid * 32 + (lane & 7) + ((lane >> 3) & 1) * 8;
    const int qlcol = (lane >> 4) * 8;
    const int brow = (lane & 7) + ((lane >> 4) & 1) * 8;
    const int bcol = ((lane >> 3) & 1) * 8;
    const int vrow = (lane & 7) + ((lane >> 3) & 1) * 8;
    const int vcol = ((lane >> 4) & 1) * 8;

    const half2 sc2 = __float2half2_rn(SC_);
    constexpr int T = N_ / 64;   // 48

    for (;;) {
        if (tid == 0) s_idx = atomicAdd(&g_attn_ctr, 1);
        __syncthreads();
        const int item = s_idx;
        if (item >= ATTN_ITEMS) break;
        const int bh = item / (N_ / 128);
        const int qb = item % (N_ / 128);
        const int b = bh / H_, h = bh % H_;

        const size_t qgbase = ((size_t)(b * N_ + qb * 128)) * QKVD + h * HD_;
        const size_t kgbase = (size_t)(b * N_) * QKVD + C_ + h * HD_;
        const size_t vgbase = kgbase + C_;

        auto stage = [&](int kt, int buf) {
#pragma unroll
            for (int i = 0; i < 4; i++) {
                int idx = tid + i * 128;
                int r = idx >> 3, c = idx & 7;
                size_t roff = (size_t)(kt + r) * QKVD + c * 8;
                cpa16(ksb + (buf * 64 * KSTR + r * KSTR + c * 8) * 2, qkvh + kgbase + roff);
                cpa16(vsb + (buf * 64 * KSTR + r * KSTR + c * 8) * 2, qkvh + vgbase + roff);
            }
            CP_COMMIT();
        };

#pragma unroll
        for (int i = 0; i < 8; i++) {
            int idx = tid + i * 128;
            int r = idx >> 3, c = idx & 7;
            cpa16(qsb + (r * KSTR + c * 8) * 2, qkvh + qgbase + (size_t)r * QKVD + c * 8);
        }
        stage(0, 0);
        stage(64, 1);

        float o[2][8][4];
#pragma unroll
        for (int mt = 0; mt < 2; mt++)
#pragma unroll
            for (int nt = 0; nt < 8; nt++)
#pragma unroll
                for (int r = 0; r < 4; r++) o[mt][nt][r] = 0.f;
        float mv[2][2] = {{-1e30f, -1e30f}, {-1e30f, -1e30f}};
        float lv[2][2] = {{0.f, 0.f}, {0.f, 0.f}};

        for (int t = 0; t < T; t++) {
            if (t + 1 < T) CP_WAIT1(); else CP_WAIT0();
            __syncthreads();
            if (t + 2 < T) stage((t + 2) * 64, (t + 2) % 3);

            const uint32_t kb = ksb + (t % 3) * (64 * KSTR * 2);
            const uint32_t vb = vsb + (t % 3) * (64 * KSTR * 2);

            uint32_t s[2][8][2];
#pragma unroll
            for (int mt = 0; mt < 2; mt++)
#pragma unroll
                for (int nt = 0; nt < 8; nt++) { s[mt][nt][0] = 0u; s[mt][nt][1] = 0u; }
#pragma unroll
            for (int ks = 0; ks < 4; ks++) {
                uint32_t aq[2][4];
#pragma unroll
                for (int mt = 0; mt < 2; mt++)
                    ldsm4(aq[mt], qsb + ((qlrow + mt * 16) * KSTR + ks * 16 + qlcol) * 2);
#pragma unroll
                for (int ntp = 0; ntp < 4; ntp++) {
                    uint32_t r[4];
                    ldsm4(r, kb + ((ntp * 16 + brow) * KSTR + ks * 16 + bcol) * 2);
#pragma unroll
                    for (int mt = 0; mt < 2; mt++) {
                        mma_h16(s[mt][2 * ntp],     aq[mt], r,     s[mt][2 * ntp]);
                        mma_h16(s[mt][2 * ntp + 1], aq[mt], r + 2, s[mt][2 * ntp + 1]);
                    }
                }
            }

            float al[2][2];
#pragma unroll
            for (int mt = 0; mt < 2; mt++) {
                half2 hx0 = u2h(s[mt][0][0]), hx1 = u2h(s[mt][0][1]);
#pragma unroll
                for (int nt = 1; nt < 8; nt++) {
                    hx0 = __hmax2(hx0, u2h(s[mt][nt][0]));
                    hx1 = __hmax2(hx1, u2h(s[mt][nt][1]));
                }
                float mx0 = fmaxf(__low2float(hx0), __high2float(hx0));
                float mx1 = fmaxf(__low2float(hx1), __high2float(hx1));
                mx0 = fmaxf(mx0, __shfl_xor_sync(0xffffffffu, mx0, 1));
                mx0 = fmaxf(mx0, __shfl_xor_sync(0xffffffffu, mx0, 2));
                mx1 = fmaxf(mx1, __shfl_xor_sync(0xffffffffu, mx1, 1));
                mx1 = fmaxf(mx1, __shfl_xor_sync(0xffffffffu, mx1, 2));

                float nm0 = fmaxf(mv[mt][0], mx0), nm1 = fmaxf(mv[mt][1], mx1);
                float a0 = exp2f((mv[mt][0] - nm0) * SC_);
                float a1 = exp2f((mv[mt][1] - nm1) * SC_);
                mv[mt][0] = nm0; mv[mt][1] = nm1;
                al[mt][0] = a0; al[mt][1] = a1;

                if (!__all_sync(0xffffffffu, (a0 == 1.f) & (a1 == 1.f))) {
#pragma unroll
                    for (int nt = 0; nt < 8; nt++) {
                        o[mt][nt][0] *= a0; o[mt][nt][1] *= a0;
                        o[mt][nt][2] *= a1; o[mt][nt][3] *= a1;
                    }
                }
                half2 nm02 = __float2half2_rn(nm0);
                half2 nm12 = __float2half2_rn(nm1);
#pragma unroll
                for (int nt = 0; nt < 8; nt++) {
                    s[mt][nt][0] = ex2h2(h2u(__hmul2(__hsub2(u2h(s[mt][nt][0]), nm02), sc2)));
                    s[mt][nt][1] = ex2h2(h2u(__hmul2(__hsub2(u2h(s[mt][nt][1]), nm12), sc2)));
                }

                // row-sum on ALU pipe (pairwise fp16, then fp32 quad reduce)
                half2 pa0 = __hadd2(u2h(s[mt][0][0]), u2h(s[mt][1][0]));
                half2 pb0 = __hadd2(u2h(s[mt][2][0]), u2h(s[mt][3][0]));
                half2 pc0 = __hadd2(u2h(s[mt][4][0]), u2h(s[mt][5][0]));
                half2 pd0 = __hadd2(u2h(s[mt][6][0]), u2h(s[mt][7][0]));
                half2 pa1 = __hadd2(u2h(s[mt][0][1]), u2h(s[mt][1][1]));
                half2 pb1 = __hadd2(u2h(s[mt][2][1]), u2h(s[mt][3][1]));
                half2 pc1 = __hadd2(u2h(s[mt][4][1]), u2h(s[mt][5][1]));
                half2 pd1 = __hadd2(u2h(s[mt][6][1]), u2h(s[mt][7][1]));
                pa0 = __hadd2(pa0, pb0); pc0 = __hadd2(pc0, pd0);
                pa1 = __hadd2(pa1, pb1); pc1 = __hadd2(pc1, pd1);
                float2 fa0 = __half22float2(pa0), fc0 = __half22float2(pc0);
                float2 fa1 = __half22float2(pa1), fc1 = __half22float2(pc1);
                float f0 = fa0.x + fa0.y + fc0.x + fc0.y;
                float f1 = fa1.x + fa1.y + fc1.x + fc1.y;
                f0 += __shfl_xor_sync(0xffffffffu, f0, 1);
                f0 += __shfl_xor_sync(0xffffffffu, f0, 2);
                f1 += __shfl_xor_sync(0xffffffffu, f1, 1);
                f1 += __shfl_xor_sync(0xffffffffu, f1, 2);
                lv[mt][0] = lv[mt][0] * a0 + f0;
                lv[mt][1] = lv[mt][1] * a1 + f1;
            }

            // O += P V (V frags loaded once, shared by both m-tiles)
#pragma unroll
            for (int k2 = 0; k2 < 4; k2++) {
                uint32_t af[2][4];
#pragma unroll
                for (int mt = 0; mt < 2; mt++) {
                    af[mt][0] = s[mt][2 * k2][0];     af[mt][1] = s[mt][2 * k2][1];
                    af[mt][2] = s[mt][2 * k2 + 1][0]; af[mt][3] = s[mt][2 * k2 + 1][1];
                }
#pragma unroll
                for (int ntp = 0; ntp < 4; ntp++) {
                    uint32_t r[4];
                    ldsm4t(r, vb + ((k2 * 16 + vrow) * KSTR + ntp * 16 + vcol) * 2);
#pragma unroll
                    for (int mt = 0; mt < 2; mt++) {
                        mma_f16(o[mt][2 * ntp],     af[mt], r,     o[mt][2 * ntp]);
                        mma_f16(o[mt][2 * ntp + 1], af[mt], r + 2, o[mt][2 * ntp + 1]);
                    }
                }
            }
        }

        const int qrow = qb * 128 + wid * 32 + g;
#pragma unroll
        for (int mt = 0; mt < 2; mt++) {
            float inv0 = 1.f / lv[mt][0], inv1 = 1.f / lv[mt][1];
            __half* o0 = outh + (size_t)(b * N_ + qrow + mt * 16) * C_ + h * HD_;
            __half* o1 = o0 + (size_t)8 * C_;
#pragma unroll
            for (int nt = 0; nt < 8; nt++) {
                int c = nt * 8 + 2 * q;
                *(half2*)(o0 + c) = __floats2half2_rn(o[mt][nt][0] * inv0, o[mt][nt][1] * inv0);
                *(half2*)(o1 + c) = __floats2half2_rn(o[mt][nt][2] * inv1, o[mt][nt][3] * inv1);
            }
        }
    }
}

// ============================================================
// Launch orchestration
// ============================================================
extern "C" void kernel_launch(void* const* d_in, const int* in_sizes, int n_in,
                              void* d_out, int out_size) {
    const float* x      = (const float*)d_in[0];
    const float* w_qkv  = (const float*)d_in[1];
    const float* w_proj = (const float*)d_in[2];
    const float* b_proj = (const float*)d_in[3];
    const float* g1     = (const float*)d_in[4];
    const float* beta1  = (const float*)d_in[5];
    const float* g2     = (const float*)d_in[6];
    const float* beta2  = (const float*)d_in[7];
    const float* w_fc1  = (const float*)d_in[8];
    const float* b_fc1  = (const float*)d_in[9];
    const float* w_fc2  = (const float*)d_in[10];
    const float* b_fc2  = (const float*)d_in[11];
    const float* cos_x  = (const float*)d_in[12];
    const float* sin_x  = (const float*)d_in[13];
    const float* cos_y  = (const float*)d_in[14];
    const float* sin_y  = (const float*)d_in[15];
    float* out = (float*)d_out;

    __half *xnh, *qkvh, *attnh, *hh, *wqkvh, *wprojh, *wfc1h, *wfc2h;
    float* x1;
    cudaGetSymbolAddress((void**)&xnh,   g_xnh);
    cudaGetSymbolAddress((void**)&qkvh,  g_qkvh);
    cudaGetSymbolAddress((void**)&attnh, g_attnh);
    cudaGetSymbolAddress((void**)&x1,    g_x1);
    cudaGetSymbolAddress((void**)&hh,    g_hh);
    cudaGetSymbolAddress((void**)&wqkvh, g_wqkvh);
    cudaGetSymbolAddress((void**)&wprojh, g_wprojh);
    cudaGetSymbolAddress((void**)&wfc1h, g_wfc1h);
    cudaGetSymbolAddress((void**)&wfc2h, g_wfc2h);

    cudaFuncSetAttribute(gemm_h<0, 1, 1>, cudaFuncAttributeMaxDynamicSharedMemorySize, SMEM_GEMM);
    cudaFuncSetAttribute(gemm_h<0, 0, 0>, cudaFuncAttributeMaxDynamicSharedMemorySize, SMEM_GEMM);
    cudaFuncSetAttribute(gemm_h<1, 1, 0>, cudaFuncAttributeMaxDynamicSharedMemorySize, SMEM_GEMM);
    cudaFuncSetAttribute(attn_h, cudaFuncAttributeMaxDynamicSharedMemorySize, SMEM_ATTN);

    // weight conversions (single launch)
    f2h_all<<<(N8_TOT + 255) / 256, 256>>>(w_qkv, w_proj, w_fc1, w_fc2,
                                           wqkvh, wprojh, wfc1h, wfc2h);

    // 1. LN1 -> half (also zeroes the attn work counter)
    ln_h<<<M_ / 8, 256>>>(x, g1, beta1, xnh);
    // 2. QKV projection + fused 2D RoPE -> half
    gemm_h<0, 1, 1><<<dim3(QKVD / 128, M_ / 128), 128, SMEM_GEMM>>>(
        xnh, wqkvh, nullptr, nullptr, qkvh, M_, QKVD, C_, cos_x, sin_x, cos_y, sin_y);
    // 3. Attention -> half (persistent, work-stealing)
    attn_h<<<456, 128, SMEM_ATTN>>>(qkvh, attnh);
    // 4. proj + bias + residual(x) -> x1 (fp32)
    gemm_h<0, 0, 0><<<dim3(C_ / 128, M_ / 128), 128, SMEM_GEMM>>>(
        attnh, wprojh, b_proj, x, x1, M_, C_, C_, nullptr, nullptr, nullptr, nullptr);
    // 5. LN2 -> half
    ln_h<<<M_ / 8, 256>>>(x1, g2, beta2, xnh);
    // 6. FC1 + bias + GELU -> half
    gemm_h<1, 1, 0><<<dim3(4 * C_ / 128, M_ / 128), 128, SMEM_GEMM>>>(
        xnh, wfc1h, b_fc1, nullptr, hh, M_, 4 * C_, C_, nullptr, nullptr, nullptr, nullptr);
    // 7. FC2 + bias + residual(x1) -> out (fp32)
    gemm_h<0, 0, 0><<<dim3(C_ / 128, M_ / 128), 128, SMEM_GEMM>>>(
        hh, wfc2h, b_fc2, x1, out, M_, C_, 4 * C_, nullptr, nullptr, nullptr, nullptr);
}

// round 16
// speedup vs baseline: 1.0610x; 1.0124x over previous
#include <cuda_runtime.h>
#include <cuda_fp16.h>
#include <cstdint>
#include <cstddef>

constexpr int B_ = 2, N_ = 3072, C_ = 768, H_ = 12, HD_ = 64;
constexpr int M_ = B_ * N_;           // 6144
constexpr int QKVD = 3 * C_;          // 2304

// ---- static scratch ----
__device__ __half g_xnh[M_ * C_];
__device__ __half g_qkvh[(size_t)M_ * QKVD];
__device__ __half g_attnh[M_ * C_];
__device__ float  g_x1[M_ * C_];
__device__ __half g_hh[(size_t)M_ * 4 * C_];
__device__ __half g_wqkvh[QKVD * C_];
__device__ __half g_wprojh[C_ * C_];
__device__ __half g_wfc1h[4 * C_ * C_];
__device__ __half g_wfc2h[C_ * 4 * C_];
__device__ int    g_attn_ctr;

// ---- ptx helpers ----
__device__ __forceinline__ void mma_f16(float* d, const uint32_t* a,
                                        const uint32_t* b, const float* c) {
    asm volatile(
        "mma.sync.aligned.m16n8k16.row.col.f32.f16.f16.f32 "
        "{%0,%1,%2,%3},{%4,%5,%6,%7},{%8,%9},{%10,%11,%12,%13};"
        : "=f"(d[0]), "=f"(d[1]), "=f"(d[2]), "=f"(d[3])
        : "r"(a[0]), "r"(a[1]), "r"(a[2]), "r"(a[3]),
          "r"(b[0]), "r"(b[1]),
          "f"(c[0]), "f"(c[1]), "f"(c[2]), "f"(c[3]));
}
// fp16 accumulator variant (2 output regs)
__device__ __forceinline__ void mma_h16(uint32_t* d, const uint32_t* a,
                                        const uint32_t* b, const uint32_t* c) {
    asm volatile(
        "mma.sync.aligned.m16n8k16.row.col.f16.f16.f16.f16 "
        "{%0,%1},{%2,%3,%4,%5},{%6,%7},{%8,%9};"
        : "=r"(d[0]), "=r"(d[1])
        : "r"(a[0]), "r"(a[1]), "r"(a[2]), "r"(a[3]),
          "r"(b[0]), "r"(b[1]), "r"(c[0]), "r"(c[1]));
}
__device__ __forceinline__ void ldsm4(uint32_t* r, uint32_t a) {
    asm volatile("ldmatrix.sync.aligned.m8n8.x4.shared.b16 {%0,%1,%2,%3}, [%4];"
                 : "=r"(r[0]), "=r"(r[1]), "=r"(r[2]), "=r"(r[3]) : "r"(a));
}
__device__ __forceinline__ void ldsm4t(uint32_t* r, uint32_t a) {
    asm volatile("ldmatrix.sync.aligned.m8n8.x4.trans.shared.b16 {%0,%1,%2,%3}, [%4];"
                 : "=r"(r[0]), "=r"(r[1]), "=r"(r[2]), "=r"(r[3]) : "r"(a));
}
__device__ __forceinline__ void cpa16(uint32_t dst, const void* src) {
    asm volatile("cp.async.cg.shared.global [%0], [%1], 16;\n" :: "r"(dst), "l"(src));
}
#define CP_COMMIT() asm volatile("cp.async.commit_group;\n" ::: "memory")
#define CP_WAIT1()  asm volatile("cp.async.wait_group 1;\n" ::: "memory")
#define CP_WAIT0()  asm volatile("cp.async.wait_group 0;\n" ::: "memory")

__device__ __forceinline__ uint32_t h2u(half2 h) { return *(uint32_t*)&h; }
__device__ __forceinline__ half2 u2h(uint32_t u) { return *(half2*)&u; }
__device__ __forceinline__ uint32_t ex2h2(uint32_t x) {
    uint32_t r;
    asm("ex2.approx.f16x2 %0, %1;" : "=r"(r) : "r"(x));
    return r;
}

constexpr float SC_ = 0.125f * 1.44269504088896341f;

// ============================================================
// fused fp32 -> fp16 conversion for all 4 weight matrices
// ============================================================
constexpr int N8_QKV = QKVD * C_ / 8;
constexpr int N8_PRJ = C_ * C_ / 8;
constexpr int N8_FC  = 4 * C_ * C_ / 8;
constexpr int N8_TOT = N8_QKV + N8_PRJ + 2 * N8_FC;

__global__ void f2h_all(const float* __restrict__ s0, const float* __restrict__ s1,
                        const float* __restrict__ s2, const float* __restrict__ s3,
                        __half* __restrict__ d0, __half* __restrict__ d1,
                        __half* __restrict__ d2, __half* __restrict__ d3) {
    int i = blockIdx.x * blockDim.x + threadIdx.x;
    if (i >= N8_TOT) return;
    const float* s; __half* d;
    if (i < N8_QKV)                       { s = s0; d = d0; }
    else if (i < N8_QKV + N8_PRJ)         { s = s1; d = d1; i -= N8_QKV; }
    else if (i < N8_QKV + N8_PRJ + N8_FC) { s = s2; d = d2; i -= N8_QKV + N8_PRJ; }
    else                                  { s = s3; d = d3; i -= N8_QKV + N8_PRJ + N8_FC; }
    const float4* sp = (const float4*)s;
    float4 a = sp[2 * i], b = sp[2 * i + 1];
    half2 h[4] = {__floats2half2_rn(a.x, a.y), __floats2half2_rn(a.z, a.w),
                  __floats2half2_rn(b.x, b.y), __floats2half2_rn(b.z, b.w)};
    ((uint4*)d)[i] = *(uint4*)h;
}

// ============================================================
// LayerNorm: one WARP per row. Also resets attn counter.
// ============================================================
__global__ void ln_h(const float* __restrict__ x, const float* __restrict__ g,
                     const float* __restrict__ b, __half* __restrict__ out) {
    const int lane = threadIdx.x & 31;
    const int row = blockIdx.x * 8 + (threadIdx.x >> 5);
    if (row == 0 && lane == 0) g_attn_ctr = 0;

    const float2* xr = (const float2*)(x + (size_t)row * C_);
    float2 v[12];
    float s = 0.f, sq = 0.f;
#pragma unroll
    for (int j = 0; j < 12; j++) {
        v[j] = xr[lane + j * 32];
        s += v[j].x + v[j].y;
        sq += v[j].x * v[j].x + v[j].y * v[j].y;
    }
#pragma unroll
    for (int o = 16; o > 0; o >>= 1) {
        s  += __shfl_xor_sync(0xffffffffu, s, o);
        sq += __shfl_xor_sync(0xffffffffu, sq, o);
    }
    float mean = s * (1.0f / C_);
    float rstd = rsqrtf(sq * (1.0f / C_) - mean * mean + 1e-5f);
    half2* orow = (half2*)(out + (size_t)row * C_);
    const float2* gp = (const float2*)g;
    const float2* bp = (const float2*)b;
#pragma unroll
    for (int j = 0; j < 12; j++) {
        float2 gg = gp[lane + j * 32];
        float2 bb = bp[lane + j * 32];
        orow[lane + j * 32] = __floats2half2_rn(
            (v[j].x - mean) * rstd * gg.x + bb.x,
            (v[j].y - mean) * rstd * gg.y + bb.y);
    }
}

// ============================================================
// fp16 tensor-core GEMM NT: 128x128x32 block, 4 warps (2x2),
// warp tile 64x64, 3-stage cp.async, 2 blocks/SM.  (R11-proven)
// ============================================================
constexpr int ASTR = 40;
constexpr int A_STG = 128 * ASTR;
constexpr int SMEM_GEMM = 3 * 2 * A_STG * 2;   // 61440 bytes

template <int ACT, int OUTH, int ROPE>
__global__ void __launch_bounds__(128, 2)
gemm_h(const __half* __restrict__ A, const __half* __restrict__ W,
       const float* __restrict__ bias, const float* __restrict__ resid,
       void* __restrict__ Cout, int M, int Nd, int K,
       const float* __restrict__ cx, const float* __restrict__ sx,
       const float* __restrict__ cy, const float* __restrict__ sy)
{
    extern __shared__ __half sm[];
    __half* As = sm;
    __half* Ws = sm + 3 * A_STG;

    const int tid = threadIdx.x, lane = tid & 31, wid = tid >> 5;
    const int warpM = wid >> 1, warpN = wid & 1;
    const int g = lane >> 2, q = lane & 3;
    const int m0 = blockIdx.y * 128, n0 = blockIdx.x * 128;

    const uint32_t asbase = (uint32_t)__cvta_generic_to_shared(As);
    const uint32_t wsbase = (uint32_t)__cvta_generic_to_shared(Ws);

    auto stage = [&](int t, int s) {
        int k0 = t * 32;
        uint32_t ab = asbase + s * (A_STG * 2);
        uint32_t wb = wsbase + s * (A_STG * 2);
#pragma unroll
        for (int i = 0; i < 4; i++) {
            int idx = tid + i * 128;
            int r = idx >> 2, c = (idx & 3) * 8;
            cpa16(ab + (r * ASTR + c) * 2, A + (size_t)(m0 + r) * K + k0 + c);
            cpa16(wb + (r * ASTR + c) * 2, W + (size_t)(n0 + r) * K + k0 + c);
        }
    };

    float acc[4][8][4];
#pragma unroll
    for (int mt = 0; mt < 4; mt++)
#pragma unroll
        for (int nt = 0; nt < 8; nt++)
#pragma unroll
            for (int r = 0; r < 4; r++) acc[mt][nt][r] = 0.f;

    const int T = K / 32;
    stage(0, 0); CP_COMMIT();
    stage(1, 1); CP_COMMIT();

    const int lrow = warpM * 64 + (lane & 7) + ((lane >> 3) & 1) * 8;
    const int lcol = (lane >> 4) * 8;
    const int brow = (lane & 7) + ((lane >> 4) & 1) * 8;
    const int bcol = ((lane >> 3) & 1) * 8;

    for (int t = 0; t < T; t++) {
        CP_WAIT1();
        __syncthreads();
        if (t + 2 < T) stage(t + 2, (t + 2) % 3);
        CP_COMMIT();
        const int s = t % 3;
        const uint32_t ab = asbase + s * (A_STG * 2);
        const uint32_t wb = wsbase + s * (A_STG * 2);
#pragma unroll
        for (int kk = 0; kk < 32; kk += 16) {
            uint32_t af[4][4];
#pragma unroll
            for (int mt = 0; mt < 4; mt++)
                ldsm4(af[mt], ab + ((lrow + mt * 16) * ASTR + lcol + kk) * 2);
            uint32_t bf[8][2];
#pragma unroll
            for (int ntp = 0; ntp < 4; ntp++) {
                uint32_t r[4];
                ldsm4(r, wb + ((warpN * 64 + ntp * 16 + brow) * ASTR + kk + bcol) * 2);
                bf[2 * ntp][0] = r[0]; bf[2 * ntp][1] = r[1];
                bf[2 * ntp + 1][0] = r[2]; bf[2 * ntp + 1][1] = r[3];
            }
#pragma unroll
            for (int mt = 0; mt < 4; mt++)
#pragma unroll
                for (int nt = 0; nt < 8; nt++)
                    mma_f16(acc[mt][nt], af[mt], bf[nt], acc[mt][nt]);
        }
    }

    if (ROPE) {
        __half* O = (__half*)Cout;
        const int chunk = n0 + warpN * 64;
        const bool qk = chunk < 2 * C_;
#pragma unroll
        for (int mt = 0; mt < 4; mt++) {
            int m = m0 + warpM * 64 + mt * 16 + g;
            int ntok = m % N_;
            if (qk) {
#pragma unroll
                for (int base = 0; base < 8; base += 4) {
                    const float* ct = base ? cx : cy;
                    const float* st = base ? sx : sy;
#pragma unroll
                    for (int p = 0; p < 2; p++) {
                        int j = p * 8 + 2 * q;
                        float2 c0 = *(const float2*)&ct[ntok * 32 + j];
                        float2 s0 = *(const float2*)&st[ntok * 32 + j];
                        float2 c1 = *(const float2*)&ct[(ntok + 8) * 32 + j];
                        float2 s1 = *(const float2*)&st[(ntok + 8) * 32 + j];
                        float* lo = acc[mt][base + p];
                        float* hi = acc[mt][base + p + 2];
                        float t1, t2;
                        t1 = lo[0]; t2 = hi[0];
                        lo[0] = t1 * c0.x - t2 * s0.x; hi[0] = t2 * c0.x + t1 * s0.x;
                        t1 = lo[1]; t2 = hi[1];
                        lo[1] = t1 * c0.y - t2 * s0.y; hi[1] = t2 * c0.y + t1 * s0.y;
                        t1 = lo[2]; t2 = hi[2];
                        lo[2] = t1 * c1.x - t2 * s1.x; hi[2] = t2 * c1.x + t1 * s1.x;
                        t1 = lo[3]; t2 = hi[3];
                        lo[3] = t1 * c1.y - t2 * s1.y; hi[3] = t2 * c1.y + t1 * s1.y;
                    }
                }
            }
#pragma unroll
            for (int nt = 0; nt < 8; nt++) {
                int c = chunk + nt * 8 + 2 * q;
                size_t i0 = (size_t)m * Nd + c, i1 = (size_t)(m + 8) * Nd + c;
                *(half2*)(O + i0) = __floats2half2_rn(acc[mt][nt][0], acc[mt][nt][1]);
                *(half2*)(O + i1) = __floats2half2_rn(acc[mt][nt][2], acc[mt][nt][3]);
            }
        }
        return;
    }

#pragma unroll
    for (int mt = 0; mt < 4; mt++) {
#pragma unroll
        for (int nt = 0; nt < 8; nt++) {
            int m = m0 + warpM * 64 + mt * 16 + g;
            int c = n0 + warpN * 64 + nt * 8 + 2 * q;
            float bv0 = bias ? bias[c] : 0.f;
            float bv1 = bias ? bias[c + 1] : 0.f;
            float v0 = acc[mt][nt][0] + bv0, v1 = acc[mt][nt][1] + bv1;
            float v2 = acc[mt][nt][2] + bv0, v3 = acc[mt][nt][3] + bv1;
            if (ACT == 1) {
                v0 = 0.5f * v0 * (1.0f + erff(v0 * 0.70710678118654752f));
                v1 = 0.5f * v1 * (1.0f + erff(v1 * 0.70710678118654752f));
                v2 = 0.5f * v2 * (1.0f + erff(v2 * 0.70710678118654752f));
                v3 = 0.5f * v3 * (1.0f + erff(v3 * 0.70710678118654752f));
            }
            size_t i0 = (size_t)m * Nd + c, i1 = (size_t)(m + 8) * Nd + c;
            if (OUTH) {
                __half* O = (__half*)Cout;
                *(half2*)(O + i0) = __floats2half2_rn(v0, v1);
                *(half2*)(O + i1) = __floats2half2_rn(v2, v3);
            } else {
                float* O = (float*)Cout;
                if (resid) {
                    float2 r0 = *(const float2*)&resid[i0];
                    float2 r1 = *(const float2*)&resid[i1];
                    v0 += r0.x; v1 += r0.y; v2 += r1.x; v3 += r1.y;
                }
                *(float2*)&O[i0] = make_float2(v0, v1);
                *(float2*)&O[i1] = make_float2(v2, v3);
            }
        }
    }
}

// ============================================================
// Flash attention, persistent work-stealing blocks. (R11 exact)
// 4 warps/block, 32 q-rows per warp, Q staged in smem,
// S in fp16 accumulators, mma ones row-sum, 3-stage K/V ring,
// one barrier per tile, 3 CTAs/SM.
// ============================================================
constexpr int KSTR = 72;
constexpr int ATTN_ITEMS = B_ * H_ * (N_ / 128);   // 576
constexpr int Q_OFF = 0;
constexpr int K_OFF = 128 * KSTR;
constexpr int V_OFF = K_OFF + 3 * 64 * KSTR;
constexpr int SMEM_ATTN = (V_OFF + 3 * 64 * KSTR) * 2;  // 73728 bytes

__global__ void __launch_bounds__(128, 3)
attn_h(const __half* __restrict__ qkvh, __half* __restrict__ outh)
{
    extern __shared__ __half smA[];
    __shared__ int s_idx;

    const int tid = threadIdx.x, lane = tid & 31, wid = tid >> 5;
    const int g = lane >> 2, q = lane & 3;

    const uint32_t base = (uint32_t)__cvta_generic_to_shared(smA);
    const uint32_t qsb = base + Q_OFF * 2;
    const uint32_t ksb = base + K_OFF * 2;
    const uint32_t vsb = base + V_OFF * 2;

    const int qlrow = wid * 32 + (lane & 7) + ((lane >> 3) & 1) * 8;
    const int qlcol = (lane >> 4) * 8;
    const int brow = (lane & 7) + ((lane >> 4) & 1) * 8;
    const int bcol = ((lane >> 3) & 1) * 8;
    const int vrow = (lane & 7) + ((lane >> 3) & 1) * 8;
    const int vcol = ((lane >> 4) & 1) * 8;

    const half2 sc2 = __float2half2_rn(SC_);
    const uint32_t ones2[2] = {0x3C003C00u, 0x3C003C00u};
    constexpr int T = N_ / 64;   // 48

    for (;;) {
        if (tid == 0) s_idx = atomicAdd(&g_attn_ctr, 1);
        __syncthreads();
        const int item = s_idx;
        if (item >= ATTN_ITEMS) break;
        const int bh = item / (N_ / 128);
        const int qb = item % (N_ / 128);
        const int b = bh / H_, h = bh % H_;

        const size_t qgbase = ((size_t)(b * N_ + qb * 128)) * QKVD + h * HD_;
        const size_t kgbase = (size_t)(b * N_) * QKVD + C_ + h * HD_;
        const size_t vgbase = kgbase + C_;

        auto stage = [&](int kt, int buf) {
#pragma unroll
            for (int i = 0; i < 4; i++) {
                int idx = tid + i * 128;
                int r = idx >> 3, c = idx & 7;
                size_t roff = (size_t)(kt + r) * QKVD + c * 8;
                cpa16(ksb + (buf * 64 * KSTR + r * KSTR + c * 8) * 2, qkvh + kgbase + roff);
                cpa16(vsb + (buf * 64 * KSTR + r * KSTR + c * 8) * 2, qkvh + vgbase + roff);
            }
            CP_COMMIT();
        };

#pragma unroll
        for (int i = 0; i < 8; i++) {
            int idx = tid + i * 128;
            int r = idx >> 3, c = idx & 7;
            cpa16(qsb + (r * KSTR + c * 8) * 2, qkvh + qgbase + (size_t)r * QKVD + c * 8);
        }
        stage(0, 0);
        stage(64, 1);

        float o[2][8][4];
#pragma unroll
        for (int mt = 0; mt < 2; mt++)
#pragma unroll
            for (int nt = 0; nt < 8; nt++)
#pragma unroll
                for (int r = 0; r < 4; r++) o[mt][nt][r] = 0.f;
        float mv[2][2] = {{-1e30f, -1e30f}, {-1e30f, -1e30f}};
        float lv[2][2] = {{0.f, 0.f}, {0.f, 0.f}};

        for (int t = 0; t < T; t++) {
            if (t + 1 < T) CP_WAIT1(); else CP_WAIT0();
            __syncthreads();
            if (t + 2 < T) stage((t + 2) * 64, (t + 2) % 3);

            const uint32_t kb = ksb + (t % 3) * (64 * KSTR * 2);
            const uint32_t vb = vsb + (t % 3) * (64 * KSTR * 2);

            uint32_t s[2][8][2];
#pragma unroll
            for (int mt = 0; mt < 2; mt++)
#pragma unroll
                for (int nt = 0; nt < 8; nt++) { s[mt][nt][0] = 0u; s[mt][nt][1] = 0u; }
#pragma unroll
            for (int ks = 0; ks < 4; ks++) {
                uint32_t aq[2][4];
#pragma unroll
                for (int mt = 0; mt < 2; mt++)
                    ldsm4(aq[mt], qsb + ((qlrow + mt * 16) * KSTR + ks * 16 + qlcol) * 2);
#pragma unroll
                for (int ntp = 0; ntp < 4; ntp++) {
                    uint32_t r[4];
                    ldsm4(r, kb + ((ntp * 16 + brow) * KSTR + ks * 16 + bcol) * 2);
#pragma unroll
                    for (int mt = 0; mt < 2; mt++) {
                        mma_h16(s[mt][2 * ntp],     aq[mt], r,     s[mt][2 * ntp]);
                        mma_h16(s[mt][2 * ntp + 1], aq[mt], r + 2, s[mt][2 * ntp + 1]);
                    }
                }
            }

            float al[2][2];
#pragma unroll
            for (int mt = 0; mt < 2; mt++) {
                half2 hx0 = u2h(s[mt][0][0]), hx1 = u2h(s[mt][0][1]);
#pragma unroll
                for (int nt = 1; nt < 8; nt++) {
                    hx0 = __hmax2(hx0, u2h(s[mt][nt][0]));
                    hx1 = __hmax2(hx1, u2h(s[mt][nt][1]));
                }
                float mx0 = fmaxf(__low2float(hx0), __high2float(hx0));
                float mx1 = fmaxf(__low2float(hx1), __high2float(hx1));
                mx0 = fmaxf(mx0, __shfl_xor_sync(0xffffffffu, mx0, 1));
                mx0 = fmaxf(mx0, __shfl_xor_sync(0xffffffffu, mx0, 2));
                mx1 = fmaxf(mx1, __shfl_xor_sync(0xffffffffu, mx1, 1));
                mx1 = fmaxf(mx1, __shfl_xor_sync(0xffffffffu, mx1, 2));

                float nm0 = fmaxf(mv[mt][0], mx0), nm1 = fmaxf(mv[mt][1], mx1);
                float a0 = exp2f((mv[mt][0] - nm0) * SC_);
                float a1 = exp2f((mv[mt][1] - nm1) * SC_);
                mv[mt][0] = nm0; mv[mt][1] = nm1;
                al[mt][0] = a0; al[mt][1] = a1;

                if (!__all_sync(0xffffffffu, (a0 == 1.f) & (a1 == 1.f))) {
#pragma unroll
                    for (int nt = 0; nt < 8; nt++) {
                        o[mt][nt][0] *= a0; o[mt][nt][1] *= a0;
                        o[mt][nt][2] *= a1; o[mt][nt][3] *= a1;
                    }
                }
                half2 nm02 = __float2half2_rn(nm0);
                half2 nm12 = __float2half2_rn(nm1);
#pragma unroll
                for (int nt = 0; nt < 8; nt++) {
                    s[mt][nt][0] = ex2h2(h2u(__hmul2(__hsub2(u2h(s[mt][nt][0]), nm02), sc2)));
                    s[mt][nt][1] = ex2h2(h2u(__hmul2(__hsub2(u2h(s[mt][nt][1]), nm12), sc2)));
                }
            }

            // O += P V (V frags loaded once); row-sum via mma ones
            float fs[2][4] = {{0.f, 0.f, 0.f, 0.f}, {0.f, 0.f, 0.f, 0.f}};
#pragma unroll
            for (int k2 = 0; k2 < 4; k2++) {
                uint32_t af[2][4];
#pragma unroll
                for (int mt = 0; mt < 2; mt++) {
                    af[mt][0] = s[mt][2 * k2][0];     af[mt][1] = s[mt][2 * k2][1];
                    af[mt][2] = s[mt][2 * k2 + 1][0]; af[mt][3] = s[mt][2 * k2 + 1][1];
                    mma_f16(fs[mt], af[mt], ones2, fs[mt]);
                }
#pragma unroll
                for (int ntp = 0; ntp < 4; ntp++) {
                    uint32_t r[4];
                    ldsm4t(r, vb + ((k2 * 16 + vrow) * KSTR + ntp * 16 + vcol) * 2);
#pragma unroll
                    for (int mt = 0; mt < 2; mt++) {
                        mma_f16(o[mt][2 * ntp],     af[mt], r,     o[mt][2 * ntp]);
                        mma_f16(o[mt][2 * ntp + 1], af[mt], r + 2, o[mt][2 * ntp + 1]);
                    }
                }
            }
#pragma unroll
            for (int mt = 0; mt < 2; mt++) {
                lv[mt][0] = lv[mt][0] * al[mt][0] + fs[mt][0];
                lv[mt][1] = lv[mt][1] * al[mt][1] + fs[mt][2];
            }
        }

        const int qrow = qb * 128 + wid * 32 + g;
#pragma unroll
        for (int mt = 0; mt < 2; mt++) {
            float inv0 = 1.f / lv[mt][0], inv1 = 1.f / lv[mt][1];
            __half* o0 = outh + (size_t)(b * N_ + qrow + mt * 16) * C_ + h * HD_;
            __half* o1 = o0 + (size_t)8 * C_;
#pragma unroll
            for (int nt = 0; nt < 8; nt++) {
                int c = nt * 8 + 2 * q;
                *(half2*)(o0 + c) = __floats2half2_rn(o[mt][nt][0] * inv0, o[mt][nt][1] * inv0);
                *(half2*)(o1 + c) = __floats2half2_rn(o[mt][nt][2] * inv1, o[mt][nt][3] * inv1);
            }
        }
    }
}

// ============================================================
// Launch orchestration
// ============================================================
extern "C" void kernel_launch(void* const* d_in, const int* in_sizes, int n_in,
                              void* d_out, int out_size) {
    const float* x      = (const float*)d_in[0];
    const float* w_qkv  = (const float*)d_in[1];
    const float* w_proj = (const float*)d_in[2];
    const float* b_proj = (const float*)d_in[3];
    const float* g1     = (const float*)d_in[4];
    const float* beta1  = (const float*)d_in[5];
    const float* g2     = (const float*)d_in[6];
    const float* beta2  = (const float*)d_in[7];
    const float* w_fc1  = (const float*)d_in[8];
    const float* b_fc1  = (const float*)d_in[9];
    const float* w_fc2  = (const float*)d_in[10];
    const float* b_fc2  = (const float*)d_in[11];
    const float* cos_x  = (const float*)d_in[12];
    const float* sin_x  = (const float*)d_in[13];
    const float* cos_y  = (const float*)d_in[14];
    const float* sin_y  = (const float*)d_in[15];
    float* out = (float*)d_out;

    __half *xnh, *qkvh, *attnh, *hh, *wqkvh, *wprojh, *wfc1h, *wfc2h;
    float* x1;
    cudaGetSymbolAddress((void**)&xnh,   g_xnh);
    cudaGetSymbolAddress((void**)&qkvh,  g_qkvh);
    cudaGetSymbolAddress((void**)&attnh, g_attnh);
    cudaGetSymbolAddress((void**)&x1,    g_x1);
    cudaGetSymbolAddress((void**)&hh,    g_hh);
    cudaGetSymbolAddress((void**)&wqkvh, g_wqkvh);
    cudaGetSymbolAddress((void**)&wprojh, g_wprojh);
    cudaGetSymbolAddress((void**)&wfc1h, g_wfc1h);
    cudaGetSymbolAddress((void**)&wfc2h, g_wfc2h);

    cudaFuncSetAttribute(gemm_h<0, 1, 1>, cudaFuncAttributeMaxDynamicSharedMemorySize, SMEM_GEMM);
    cudaFuncSetAttribute(gemm_h<0, 0, 0>, cudaFuncAttributeMaxDynamicSharedMemorySize, SMEM_GEMM);
    cudaFuncSetAttribute(gemm_h<1, 1, 0>, cudaFuncAttributeMaxDynamicSharedMemorySize, SMEM_GEMM);
    cudaFuncSetAttribute(attn_h, cudaFuncAttributeMaxDynamicSharedMemorySize, SMEM_ATTN);

    // weight conversions (single launch)
    f2h_all<<<(N8_TOT + 255) / 256, 256>>>(w_qkv, w_proj, w_fc1, w_fc2,
                                           wqkvh, wprojh, wfc1h, wfc2h);

    // 1. LN1 -> half (also zeroes the attn work counter)
    ln_h<<<M_ / 8, 256>>>(x, g1, beta1, xnh);
    // 2. QKV projection + fused 2D RoPE -> half
    gemm_h<0, 1, 1><<<dim3(QKVD / 128, M_ / 128), 128, SMEM_GEMM>>>(
        xnh, wqkvh, nullptr, nullptr, qkvh, M_, QKVD, C_, cos_x, sin_x, cos_y, sin_y);
    // 3. Attention -> half (persistent, work-stealing)
    attn_h<<<456, 128, SMEM_ATTN>>>(qkvh, attnh);
    // 4. proj + bias + residual(x) -> x1 (fp32)
    gemm_h<0, 0, 0><<<dim3(C_ / 128, M_ / 128), 128, SMEM_GEMM>>>(
        attnh, wprojh, b_proj, x, x1, M_, C_, C_, nullptr, nullptr, nullptr, nullptr);
    // 5. LN2 -> half
    ln_h<<<M_ / 8, 256>>>(x1, g2, beta2, xnh);
    // 6. FC1 + bias + GELU -> half
    gemm_h<1, 1, 0><<<dim3(4 * C_ / 128, M_ / 128), 128, SMEM_GEMM>>>(
        xnh, wfc1h, b_fc1, nullptr, hh, M_, 4 * C_, C_, nullptr, nullptr, nullptr, nullptr);
    // 7. FC2 + bias + residual(x1) -> out (fp32)
    gemm_h<0, 0, 0><<<dim3(C_ / 128, M_ / 128), 128, SMEM_GEMM>>>(
        hh, wfc2h, b_fc2, x1, out, M_, C_, 4 * C_, nullptr, nullptr, nullptr, nullptr);
}